// round 14
// baseline (speedup 1.0000x reference)
#include <cuda_runtime.h>
#include <cuda_bf16.h>
#include <cstdint>

// ============================================================================
// Shapes (fixed): B=8, L=S=1024, G=64, D=1024, H=16, d_head=64
// compute_103 PTX: no tcgen05; mma.sync bf16 with hi/lo split precision.
// This round: attention warp m-tile 16 -> 32 rows (q-tile 256), cutting
// K'/V ldmatrix per MMA by 37%. GEMM reverted to the round-6 (930.7us) config.
// ============================================================================

#define D_MODEL 1024
#define NB 8
#define NL 1024
#define NG 64
#define NH 16
#define DH 64

typedef __nv_bfloat16 bf16;

// -------------------- scratch (device globals; no allocation) ---------------
__device__ float g_K  [NB * NL * D_MODEL];
__device__ float g_RQ [NB * NG * D_MODEL];
__device__ float g_RK [NB * NG * D_MODEL];
__device__ float g_WEP[NB * NH * DH * DH];
__device__ bf16 g_QAhi[NB * NL * D_MODEL];
__device__ bf16 g_QAlo[NB * NL * D_MODEL];
__device__ bf16 g_KAhi[NB * NL * D_MODEL];
__device__ bf16 g_KAlo[NB * NL * D_MODEL];
__device__ bf16 g_VAhi[NB * NL * D_MODEL];
__device__ bf16 g_VAlo[NB * NL * D_MODEL];
__device__ bf16 g_RAhi[NB * NG * D_MODEL];
__device__ bf16 g_RAlo[NB * NG * D_MODEL];
__device__ bf16 g_WQhi[D_MODEL * D_MODEL];
__device__ bf16 g_WQlo[D_MODEL * D_MODEL];
__device__ bf16 g_WKhi[D_MODEL * D_MODEL];
__device__ bf16 g_WKlo[D_MODEL * D_MODEL];
__device__ bf16 g_WVhi[D_MODEL * D_MODEL];
__device__ bf16 g_WVlo[D_MODEL * D_MODEL];
__device__ bf16 g_WLQhi[D_MODEL * D_MODEL];
__device__ bf16 g_WLQlo[D_MODEL * D_MODEL];
__device__ bf16 g_WLKhi[D_MODEL * D_MODEL];
__device__ bf16 g_WLKlo[D_MODEL * D_MODEL];
__device__ bf16 g_WOhi[D_MODEL * D_MODEL];
__device__ bf16 g_WOlo[D_MODEL * D_MODEL];
__device__ bf16 g_Qhi[NB * NL * D_MODEL];
__device__ bf16 g_Qlo[NB * NL * D_MODEL];
__device__ bf16 g_Vhi[NB * NL * D_MODEL];
__device__ bf16 g_Vlo[NB * NL * D_MODEL];
__device__ bf16 g_KPhi[NB * NH * NL * DH];
__device__ bf16 g_KPlo[NB * NH * NL * DH];
__device__ bf16 g_OThi[NB * NL * D_MODEL];
__device__ bf16 g_OTlo[NB * NL * D_MODEL];

// ============================================================================
// PTX helpers
// ============================================================================
__device__ __forceinline__ uint32_t smem_u32(const void* p) {
    uint32_t a;
    asm("{ .reg .u64 t; cvta.to.shared.u64 t, %1; cvt.u32.u64 %0, t; }" : "=r"(a) : "l"(p));
    return a;
}
#define CP_ASYNC16(dst, src) \
    asm volatile("cp.async.cg.shared.global [%0], [%1], 16;" :: "r"(dst), "l"(src))
#define CP_COMMIT() asm volatile("cp.async.commit_group;" ::: "memory")
#define CP_WAIT(n)  asm volatile("cp.async.wait_group %0;" :: "n"(n) : "memory")

__device__ __forceinline__ void ldmx4(uint32_t* r, uint32_t addr) {
    asm volatile("ldmatrix.sync.aligned.m8n8.x4.shared.b16 {%0,%1,%2,%3}, [%4];"
                 : "=r"(r[0]), "=r"(r[1]), "=r"(r[2]), "=r"(r[3]) : "r"(addr));
}
__device__ __forceinline__ void ldmx4t(uint32_t* r, uint32_t addr) {
    asm volatile("ldmatrix.sync.aligned.m8n8.x4.trans.shared.b16 {%0,%1,%2,%3}, [%4];"
                 : "=r"(r[0]), "=r"(r[1]), "=r"(r[2]), "=r"(r[3]) : "r"(addr));
}
__device__ __forceinline__ void mma_bf16(float* c, const uint32_t* a, const uint32_t* b) {
    asm volatile(
        "mma.sync.aligned.m16n8k16.row.col.f32.bf16.bf16.f32 "
        "{%0,%1,%2,%3}, {%4,%5,%6,%7}, {%8,%9}, {%0,%1,%2,%3};"
        : "+f"(c[0]), "+f"(c[1]), "+f"(c[2]), "+f"(c[3])
        : "r"(a[0]), "r"(a[1]), "r"(a[2]), "r"(a[3]), "r"(b[0]), "r"(b[1]));
}
__device__ __forceinline__ uint32_t pack_bf16(float lo, float hi) {
    __nv_bfloat162 p = __floats2bfloat162_rn(lo, hi);
    return *(uint32_t*)&p;
}
__device__ __forceinline__ void split_pack(float x, float y, uint32_t& hi, uint32_t& lo) {
    bf16 hx = __float2bfloat16_rn(x), hy = __float2bfloat16_rn(y);
    hi = pack_bf16(__bfloat162float(hx), __bfloat162float(hy));
    __nv_bfloat162 hp; *(uint32_t*)&hp = hi;
    lo = pack_bf16(x - __bfloat162float(hp.x), y - __bfloat162float(hp.y));
}

// ============================================================================
// Conversion kernels
// ============================================================================
__global__ __launch_bounds__(256)
void conv_hilo_kernel(const float* __restrict__ in, bf16* __restrict__ hi,
                      bf16* __restrict__ lo, int n)
{
    int i = (blockIdx.x * 256 + threadIdx.x) * 4;
    if (i >= n) return;
    float4 v = *(const float4*)(in + i);
    uint32_t h0, l0, h1, l1;
    split_pack(v.x, v.y, h0, l0);
    split_pack(v.z, v.w, h1, l1);
    *(uint32_t*)(hi + i) = h0; *(uint32_t*)(hi + i + 2) = h1;
    *(uint32_t*)(lo + i) = l0; *(uint32_t*)(lo + i + 2) = l1;
}

__global__ __launch_bounds__(256)
void conv_wt_kernel(const float* __restrict__ W, bf16* __restrict__ th,
                    bf16* __restrict__ tl)
{
    __shared__ float t[32][33];
    int bn = blockIdx.x * 32, bk = blockIdx.y * 32;
    int tx = threadIdx.x & 31, ty = threadIdx.x >> 5;
    #pragma unroll
    for (int j = 0; j < 32; j += 8)
        t[ty + j][tx] = W[(size_t)(bk + ty + j) * D_MODEL + bn + tx];
    __syncthreads();
    #pragma unroll
    for (int j = 0; j < 32; j += 8) {
        float v = t[tx][ty + j];
        bf16 h = __float2bfloat16_rn(v);
        size_t o = (size_t)(bn + ty + j) * D_MODEL + bk + tx;
        th[o] = h;
        tl[o] = __float2bfloat16_rn(v - __bfloat162float(h));
    }
}

// ============================================================================
// mma.sync split-bf16 GEMM — exact round-6 (930.7us) configuration:
// 128x128 tile, 256 threads (8 warps 4m x 2n, warp 32x64), 3-stage pipeline.
// ============================================================================
#define ARR_BYTES   16384
#define STAGE_BYTES (4 * ARR_BYTES)
#define GEMM_SMEM   (3 * STAGE_BYTES)

__global__ __launch_bounds__(256, 1)
void gemm_mma_kernel(const bf16* __restrict__ Ahi, const bf16* __restrict__ Alo,
                     const bf16* __restrict__ Bhi, const bf16* __restrict__ Blo,
                     float* __restrict__ Cf, const float* __restrict__ bias,
                     bf16* __restrict__ Chi, bf16* __restrict__ Clo,
                     int M, int N, int K)
{
    extern __shared__ char smem[];
    const uint32_t sbase = smem_u32(smem);
    const int tid  = threadIdx.x;
    const int wid  = tid >> 5, lane = tid & 31;
    const int wm   = wid & 3;
    const int wn   = wid >> 2;
    const int m0   = blockIdx.y * 128;
    const int n0   = blockIdx.x * 128;
    const int nchunks = K >> 6;

    const bf16* srcs[4] = { Ahi + (size_t)m0 * K, Alo + (size_t)m0 * K,
                            Bhi + (size_t)n0 * K, Blo + (size_t)n0 * K };

    auto issue = [&](int c, int s) {
        const uint32_t stb = sbase + s * STAGE_BYTES;
        #pragma unroll
        for (int a = 0; a < 4; a++) {
            const bf16* src = srcs[a] + c * 64;
            const uint32_t ab = stb + a * ARR_BYTES;
            #pragma unroll
            for (int i = 0; i < 4; i++) {
                int u   = tid + i * 256;
                int row = u >> 3, c8 = u & 7;
                uint32_t dst = ab + row * 128 + ((c8 ^ (row & 7)) << 4);
                CP_ASYNC16(dst, src + (size_t)row * K + c8 * 8);
            }
        }
        CP_COMMIT();
    };

    issue(0, 0);
    issue(1, 1);

    float acc[2][8][4] = {};
    const int a_row0 = wm * 32 + (lane & 15);
    const int a_sub  = lane >> 4;
    const int g      = lane >> 3;
    const int b_noff = ((g & 2) << 2) + (lane & 7);
    const int b_sub  = g & 1;

    for (int c = 0; c < nchunks; c++) {
        if (c + 1 < nchunks) CP_WAIT(1);
        else                 CP_WAIT(0);
        __syncthreads();
        if (c + 2 < nchunks) issue(c + 2, (c + 2) % 3);

        const uint32_t stb = sbase + (c % 3) * STAGE_BYTES;
        const uint32_t Ah = stb, Al = stb + ARR_BYTES;
        const uint32_t Bh = stb + 2 * ARR_BYTES, Bl = stb + 3 * ARR_BYTES;

        #pragma unroll
        for (int k16 = 0; k16 < 4; k16++) {
            const int kc = k16 * 2;
            uint32_t ah[2][4], al[2][4], bh[4][4], bl[4][4];
            #pragma unroll
            for (int mi = 0; mi < 2; mi++) {
                int row = a_row0 + mi * 16;
                uint32_t off = row * 128 + (((kc + a_sub) ^ (row & 7)) << 4);
                ldmx4(ah[mi], Ah + off);
                ldmx4(al[mi], Al + off);
            }
            #pragma unroll
            for (int pn = 0; pn < 4; pn++) {
                int n = wn * 64 + pn * 16 + b_noff;
                uint32_t off = n * 128 + (((kc + b_sub) ^ (n & 7)) << 4);
                ldmx4(bh[pn], Bh + off);
                ldmx4(bl[pn], Bl + off);
            }
            #pragma unroll
            for (int mi = 0; mi < 2; mi++)
                #pragma unroll
                for (int ni = 0; ni < 8; ni++) {
                    const uint32_t* bf = &bh[ni >> 1][(ni & 1) * 2];
                    const uint32_t* lf = &bl[ni >> 1][(ni & 1) * 2];
                    mma_bf16(acc[mi][ni], ah[mi], bf);
                    mma_bf16(acc[mi][ni], al[mi], bf);
                    mma_bf16(acc[mi][ni], ah[mi], lf);
                }
        }
    }

    const int tr = lane >> 2, tc = (lane & 3) * 2;
    const int rbase = m0 + wm * 32;
    const int cbase = n0 + wn * 64;
    #pragma unroll
    for (int mi = 0; mi < 2; mi++) {
        #pragma unroll
        for (int ni = 0; ni < 8; ni++) {
            int col = cbase + ni * 8 + tc;
            int r0 = rbase + mi * 16 + tr;
            if (Chi) {
                uint32_t h0, l0, h1, l1;
                split_pack(acc[mi][ni][0], acc[mi][ni][1], h0, l0);
                split_pack(acc[mi][ni][2], acc[mi][ni][3], h1, l1);
                *(uint32_t*)(Chi + (size_t)r0 * N + col)       = h0;
                *(uint32_t*)(Clo + (size_t)r0 * N + col)       = l0;
                *(uint32_t*)(Chi + (size_t)(r0 + 8) * N + col) = h1;
                *(uint32_t*)(Clo + (size_t)(r0 + 8) * N + col) = l1;
            } else {
                float bx = 0.f, by = 0.f;
                if (bias) { float2 bv = *(const float2*)(bias + col); bx = bv.x; by = bv.y; }
                float2 v0; v0.x = acc[mi][ni][0] + bx; v0.y = acc[mi][ni][1] + by;
                *(float2*)(Cf + (size_t)r0 * N + col) = v0;
                float2 v1; v1.x = acc[mi][ni][2] + bx; v1.y = acc[mi][ni][3] + by;
                *(float2*)(Cf + (size_t)(r0 + 8) * N + col) = v1;
            }
        }
    }
}

// ============================================================================
// W_ep[bh][d][e] = (1/8) * sum_g rq[b,g,h*64+d] * rk[b,g,h*64+e]
// ============================================================================
#define AP 68

__global__ __launch_bounds__(256)
void wep_kernel(const float* __restrict__ RQ, const float* __restrict__ RK,
                float* __restrict__ WEP)
{
    __shared__ float sA[64 * AP];
    __shared__ float sB[64 * AP];
    const int tid = threadIdx.x;
    const int bh  = blockIdx.x;
    const int b   = bh >> 4, h = bh & 15;
    const int ldr = tid >> 2;
    const int lds = (tid & 3) * 16;
    const float* rqg = RQ + (size_t)(b * NG) * D_MODEL + h * DH;
    const float* rkg = RK + (size_t)(b * NG) * D_MODEL + h * DH;
    #pragma unroll
    for (int s = 0; s < 4; s++) {
        *(float4*)&sA[ldr * AP + lds + s * 4] =
            *(const float4*)(rqg + (size_t)ldr * D_MODEL + lds + s * 4);
        *(float4*)&sB[ldr * AP + lds + s * 4] =
            *(const float4*)(rkg + (size_t)ldr * D_MODEL + lds + s * 4);
    }
    __syncthreads();
    const int tRow = (tid >> 4) * 4;
    const int tCol = (tid & 15) * 4;
    float acc[4][4] = {};
    #pragma unroll 8
    for (int g = 0; g < 64; g++) {
        float rm[4], rn[4];
        #pragma unroll
        for (int i = 0; i < 4; i++) rm[i] = sA[g * AP + tRow + i];
        #pragma unroll
        for (int j = 0; j < 4; j++) rn[j] = sB[g * AP + tCol + j];
        #pragma unroll
        for (int i = 0; i < 4; i++)
            #pragma unroll
            for (int j = 0; j < 4; j++)
                acc[i][j] += rm[i] * rn[j];
    }
    float* wout = WEP + (size_t)bh * (DH * DH);
    #pragma unroll
    for (int i = 0; i < 4; i++)
        #pragma unroll
        for (int j = 0; j < 4; j++)
            wout[(tRow + i) * DH + tCol + j] = acc[i][j] * 0.125f;
}

// ============================================================================
// K'[bh][s][d] = sum_e K[b][s][h*64+e] * WEP[bh][d][e]  -> hi/lo bf16
// ============================================================================
__global__ __launch_bounds__(256)
void kprime_kernel(const float* __restrict__ Kp, const float* __restrict__ WEP,
                   bf16* __restrict__ KPhi, bf16* __restrict__ KPlo)
{
    __shared__ float sK[64 * AP];
    __shared__ float sW[64 * AP];
    const int tid = threadIdx.x;
    const int st  = blockIdx.x;
    const int bh  = blockIdx.y;
    const int b   = bh >> 4, h = bh & 15;
    const int s0  = st * 64;
    const int ldr = tid >> 2;
    const int lds = (tid & 3) * 16;

    const float* kg = Kp + (size_t)(b * NL + s0) * D_MODEL + h * DH;
    const float* wg = WEP + (size_t)bh * (DH * DH);
    #pragma unroll
    for (int s = 0; s < 4; s++) {
        *(float4*)&sK[ldr * AP + lds + s * 4] =
            *(const float4*)(kg + (size_t)ldr * D_MODEL + lds + s * 4);
        *(float4*)&sW[ldr * AP + lds + s * 4] =
            *(const float4*)(wg + ldr * DH + lds + s * 4);
    }
    __syncthreads();

    const int tRow = (tid >> 4) * 4;
    const int tCol = (tid & 15) * 4;
    float acc[4][4] = {};
    #pragma unroll 8
    for (int e = 0; e < 64; e++) {
        float rm[4], rn[4];
        #pragma unroll
        for (int i = 0; i < 4; i++) rm[i] = sK[(tRow + i) * AP + e];
        #pragma unroll
        for (int j = 0; j < 4; j++) rn[j] = sW[(tCol + j) * AP + e];
        #pragma unroll
        for (int i = 0; i < 4; i++)
            #pragma unroll
            for (int j = 0; j < 4; j++)
                acc[i][j] += rm[i] * rn[j];
    }
    #pragma unroll
    for (int i = 0; i < 4; i++) {
        size_t o = (size_t)(bh * NL + s0 + tRow + i) * DH + tCol;
        uint32_t h0, l0, h1, l1;
        split_pack(acc[i][0], acc[i][1], h0, l0);
        split_pack(acc[i][2], acc[i][3], h1, l1);
        *(uint32_t*)(KPhi + o)     = h0;  *(uint32_t*)(KPlo + o)     = l0;
        *(uint32_t*)(KPhi + o + 2) = h1;  *(uint32_t*)(KPlo + o + 2) = l1;
    }
}

// ============================================================================
// Flash attention: q-tile 256 rows, 8 warps x 32 rows, 3-stage pipeline.
// Q fragments re-loaded from smem per chunk (register budget).
// smem: 3 x 32KB stages + 2 x 32KB Q planes = 160KB.
// ============================================================================
#define ATT_STAGE 32768
#define ATT_QB    32768
#define ATT_SMEM  (3 * ATT_STAGE + 2 * ATT_QB)   // 163840

__global__ __launch_bounds__(256, 1)
void attn_mma_kernel(const bf16* __restrict__ Qhi, const bf16* __restrict__ Qlo,
                     const bf16* __restrict__ KPhi, const bf16* __restrict__ KPlo,
                     const bf16* __restrict__ Vhi, const bf16* __restrict__ Vlo,
                     bf16* __restrict__ OThi, bf16* __restrict__ OTlo)
{
    extern __shared__ char smem[];
    const uint32_t sb = smem_u32(smem);
    const uint32_t QH = sb + 3 * ATT_STAGE, QL = QH + ATT_QB;
    const int tid = threadIdx.x;
    const int wid = tid >> 5, lane = tid & 31;
    const int mt = blockIdx.x;          // 0..3
    const int bh = blockIdx.y;
    const int b = bh >> 4, h = bh & 15;
    const int l0 = mt * 256;

    // Q load: 256 rows x 2 planes, 2048 16B-units/plane, 8 per thread each
    {
        const bf16* qh = Qhi + (size_t)(b * NL + l0) * D_MODEL + h * DH;
        const bf16* ql = Qlo + (size_t)(b * NL + l0) * D_MODEL + h * DH;
        #pragma unroll
        for (int i = 0; i < 8; i++) {
            int u = tid + i * 256;
            int row = u >> 3, c8 = u & 7;
            uint32_t sw = row * 128 + ((c8 ^ (row & 7)) << 4);
            CP_ASYNC16(QH + sw, qh + (size_t)row * D_MODEL + c8 * 8);
            CP_ASYNC16(QL + sw, ql + (size_t)row * D_MODEL + c8 * 8);
        }
        CP_COMMIT();
    }

    const bf16* kph = KPhi + (size_t)bh * NL * DH;
    const bf16* kpl = KPlo + (size_t)bh * NL * DH;
    const bf16* vh  = Vhi + (size_t)b * NL * D_MODEL + h * DH;
    const bf16* vl  = Vlo + (size_t)b * NL * D_MODEL + h * DH;

    auto issue_stage = [&](int nc, int s) {
        const uint32_t stb = sb + s * ATT_STAGE;
        #pragma unroll
        for (int i = 0; i < 2; i++) {
            int u = tid + i * 256;
            int row = u >> 3, c8 = u & 7;
            uint32_t sw = row * 128 + ((c8 ^ (row & 7)) << 4);
            CP_ASYNC16(stb + sw,         kph + (size_t)(nc * 64 + row) * DH + c8 * 8);
            CP_ASYNC16(stb + 8192 + sw,  kpl + (size_t)(nc * 64 + row) * DH + c8 * 8);
            CP_ASYNC16(stb + 16384 + sw, vh + (size_t)(nc * 64 + row) * D_MODEL + c8 * 8);
            CP_ASYNC16(stb + 24576 + sw, vl + (size_t)(nc * 64 + row) * D_MODEL + c8 * 8);
        }
        CP_COMMIT();
    };

    issue_stage(0, 0);
    issue_stage(1, 1);
    CP_WAIT(1);          // Q + stage0 complete
    __syncthreads();

    const int r0   = wid * 32;           // this warp's 32 q-rows
    const int fsub = lane >> 4;
    const int g      = lane >> 3;
    const int b_noff = ((g & 2) << 2) + (lane & 7);
    const int b_sub  = g & 1;

    float mM[2][2] = { { -1e30f, -1e30f }, { -1e30f, -1e30f } };
    float lS[2][2] = { { 0.f, 0.f }, { 0.f, 0.f } };
    float o[2][8][4] = {};

    for (int nc = 0; nc < 16; nc++) {
        if (nc + 1 < 16) CP_WAIT(1);
        else             CP_WAIT(0);
        __syncthreads();
        if (nc + 2 < 16) issue_stage(nc + 2, (nc + 2) % 3);
        const uint32_t stb = sb + (nc % 3) * ATT_STAGE;

        // ---- scores: 32 rows x 64 cols, 3-term split
        float sc[2][8][4] = {};
        #pragma unroll
        for (int kk = 0; kk < 4; kk++) {
            uint32_t kb[4][4], klo[4][4];
            #pragma unroll
            for (int ng = 0; ng < 4; ng++) {
                int nr = ng * 16 + b_noff;
                uint32_t off = nr * 128 + (((kk * 2 + b_sub) ^ (nr & 7)) << 4);
                ldmx4(kb[ng], stb + off);
                ldmx4(klo[ng], stb + 8192 + off);
            }
            #pragma unroll
            for (int mi = 0; mi < 2; mi++) {
                int frow = r0 + mi * 16 + (lane & 15);
                uint32_t qoff = frow * 128 + (((kk * 2 + fsub) ^ (frow & 7)) << 4);
                uint32_t qhf[4], qlf[4];
                ldmx4(qhf, QH + qoff);
                ldmx4(qlf, QL + qoff);
                #pragma unroll
                for (int ng = 0; ng < 4; ng++)
                    #pragma unroll
                    for (int hf = 0; hf < 2; hf++) {
                        float* a = sc[mi][ng * 2 + hf];
                        mma_bf16(a, qhf, &kb[ng][hf * 2]);
                        mma_bf16(a, qlf, &kb[ng][hf * 2]);
                        mma_bf16(a, qhf, &klo[ng][hf * 2]);
                    }
            }
        }

        // ---- online softmax + P packing (per mi)
        uint32_t php[2][8][2], plp[2][8][2];
        #pragma unroll
        for (int mi = 0; mi < 2; mi++) {
            float rmax0 = -1e30f, rmax1 = -1e30f;
            #pragma unroll
            for (int t = 0; t < 8; t++) {
                rmax0 = fmaxf(rmax0, fmaxf(sc[mi][t][0], sc[mi][t][1]));
                rmax1 = fmaxf(rmax1, fmaxf(sc[mi][t][2], sc[mi][t][3]));
            }
            #pragma unroll
            for (int off = 1; off <= 2; off <<= 1) {
                rmax0 = fmaxf(rmax0, __shfl_xor_sync(0xffffffffu, rmax0, off));
                rmax1 = fmaxf(rmax1, __shfl_xor_sync(0xffffffffu, rmax1, off));
            }
            float nM0 = fmaxf(mM[mi][0], rmax0), nM1 = fmaxf(mM[mi][1], rmax1);
            float cor0 = __expf(mM[mi][0] - nM0), cor1 = __expf(mM[mi][1] - nM1);
            mM[mi][0] = nM0; mM[mi][1] = nM1;

            float ps0 = 0.f, ps1 = 0.f;
            #pragma unroll
            for (int t = 0; t < 8; t++) {
                float p0 = __expf(sc[mi][t][0] - nM0), p1 = __expf(sc[mi][t][1] - nM0);
                float p2 = __expf(sc[mi][t][2] - nM1), p3 = __expf(sc[mi][t][3] - nM1);
                ps0 += p0 + p1; ps1 += p2 + p3;
                split_pack(p0, p1, php[mi][t][0], plp[mi][t][0]);
                split_pack(p2, p3, php[mi][t][1], plp[mi][t][1]);
            }
            #pragma unroll
            for (int off = 1; off <= 2; off <<= 1) {
                ps0 += __shfl_xor_sync(0xffffffffu, ps0, off);
                ps1 += __shfl_xor_sync(0xffffffffu, ps1, off);
            }
            lS[mi][0] = lS[mi][0] * cor0 + ps0;
            lS[mi][1] = lS[mi][1] * cor1 + ps1;
            #pragma unroll
            for (int t = 0; t < 8; t++) {
                o[mi][t][0] *= cor0; o[mi][t][1] *= cor0;
                o[mi][t][2] *= cor1; o[mi][t][3] *= cor1;
            }
        }

        // ---- PV: O[32][64] += P[32][64] V[64][64], 3-term
        #pragma unroll
        for (int kk = 0; kk < 4; kk++) {
            uint32_t vb[4][4], vlo[4][4];
            #pragma unroll
            for (int ng = 0; ng < 4; ng++) {
                int srow = kk * 16 + (lane & 7) + 8 * ((lane >> 3) & 1);
                uint32_t c8 = 2 * ng + (lane >> 4);
                uint32_t off = srow * 128 + ((c8 ^ (srow & 7)) << 4);
                ldmx4t(vb[ng], stb + 16384 + off);
                ldmx4t(vlo[ng], stb + 24576 + off);
            }
            #pragma unroll
            for (int mi = 0; mi < 2; mi++) {
                uint32_t pa[4]  = { php[mi][2 * kk][0], php[mi][2 * kk][1],
                                    php[mi][2 * kk + 1][0], php[mi][2 * kk + 1][1] };
                uint32_t pal[4] = { plp[mi][2 * kk][0], plp[mi][2 * kk][1],
                                    plp[mi][2 * kk + 1][0], plp[mi][2 * kk + 1][1] };
                #pragma unroll
                for (int ng = 0; ng < 4; ng++)
                    #pragma unroll
                    for (int hf = 0; hf < 2; hf++) {
                        float* c = o[mi][ng * 2 + hf];
                        mma_bf16(c, pa, &vb[ng][hf * 2]);
                        mma_bf16(c, pal, &vb[ng][hf * 2]);
                        mma_bf16(c, pa, &vlo[ng][hf * 2]);
                    }
            }
        }
    }
    __syncthreads();   // all chunks done before repurposing smem

    // ---- normalize + transpose through smem (fp32 [d][m], pitch 260)
    float* sOT = (float*)smem;
    const int orow = lane >> 2, ocol = (lane & 3) * 2;
    #pragma unroll
    for (int mi = 0; mi < 2; mi++) {
        float inv0 = 1.0f / lS[mi][0], inv1 = 1.0f / lS[mi][1];
        const int mbase = r0 + mi * 16;
        #pragma unroll
        for (int t = 0; t < 8; t++) {
            int d = t * 8 + ocol;
            sOT[(d + 0) * 260 + mbase + orow]     = o[mi][t][0] * inv0;
            sOT[(d + 1) * 260 + mbase + orow]     = o[mi][t][1] * inv0;
            sOT[(d + 0) * 260 + mbase + orow + 8] = o[mi][t][2] * inv1;
            sOT[(d + 1) * 260 + mbase + orow + 8] = o[mi][t][3] * inv1;
        }
    }
    __syncthreads();

    {
        const int d = tid >> 2;
        const int mseg = (tid & 3) * 64;
        size_t gro = (size_t)(b * NL + h * DH + d) * NL + l0 + mseg;
        #pragma unroll
        for (int j = 0; j < 64; j += 2) {
            float f0 = sOT[d * 260 + mseg + j];
            float f1 = sOT[d * 260 + mseg + j + 1];
            uint32_t hp, lp;
            split_pack(f0, f1, hp, lp);
            *(uint32_t*)(OThi + gro + j) = hp;
            *(uint32_t*)(OTlo + gro + j) = lp;
        }
    }
}

// ============================================================================
// Launch — multi-stream fork/join (graph-capture-safe), round-6 topology
// ============================================================================
extern "C" void kernel_launch(void* const* d_in, const int* in_sizes, int n_in,
                              void* d_out, int out_size)
{
    const float* queries = (const float*)d_in[0];
    const float* keys    = (const float*)d_in[1];
    const float* values  = (const float*)d_in[2];
    const float* routers = (const float*)d_in[3];
    const float* Wq      = (const float*)d_in[4];
    const float* Wk      = (const float*)d_in[5];
    const float* Wv      = (const float*)d_in[6];
    const float* Wlq     = (const float*)d_in[7];
    const float* Wlk     = (const float*)d_in[8];
    const float* Wo      = (const float*)d_in[9];
    const float* bo      = (const float*)d_in[10];
    float* out           = (float*)d_out;

    float *Kp, *RQ, *RK, *WEP;
    bf16 *QAhi, *QAlo, *KAhi, *KAlo, *VAhi, *VAlo, *RAhi, *RAlo;
    bf16 *WQhi, *WQlo, *WKhi, *WKlo, *WVhi, *WVlo, *WLQhi, *WLQlo, *WLKhi, *WLKlo, *WOhi, *WOlo;
    bf16 *Qhi, *Qlo, *Vhi, *Vlo, *KPhi, *KPlo, *OThi, *OTlo;
    cudaGetSymbolAddress((void**)&Kp,    g_K);
    cudaGetSymbolAddress((void**)&RQ,    g_RQ);
    cudaGetSymbolAddress((void**)&RK,    g_RK);
    cudaGetSymbolAddress((void**)&WEP,   g_WEP);
    cudaGetSymbolAddress((void**)&QAhi,  g_QAhi);
    cudaGetSymbolAddress((void**)&QAlo,  g_QAlo);
    cudaGetSymbolAddress((void**)&KAhi,  g_KAhi);
    cudaGetSymbolAddress((void**)&KAlo,  g_KAlo);
    cudaGetSymbolAddress((void**)&VAhi,  g_VAhi);
    cudaGetSymbolAddress((void**)&VAlo,  g_VAlo);
    cudaGetSymbolAddress((void**)&RAhi,  g_RAhi);
    cudaGetSymbolAddress((void**)&RAlo,  g_RAlo);
    cudaGetSymbolAddress((void**)&WQhi,  g_WQhi);
    cudaGetSymbolAddress((void**)&WQlo,  g_WQlo);
    cudaGetSymbolAddress((void**)&WKhi,  g_WKhi);
    cudaGetSymbolAddress((void**)&WKlo,  g_WKlo);
    cudaGetSymbolAddress((void**)&WVhi,  g_WVhi);
    cudaGetSymbolAddress((void**)&WVlo,  g_WVlo);
    cudaGetSymbolAddress((void**)&WLQhi, g_WLQhi);
    cudaGetSymbolAddress((void**)&WLQlo, g_WLQlo);
    cudaGetSymbolAddress((void**)&WLKhi, g_WLKhi);
    cudaGetSymbolAddress((void**)&WLKlo, g_WLKlo);
    cudaGetSymbolAddress((void**)&WOhi,  g_WOhi);
    cudaGetSymbolAddress((void**)&WOlo,  g_WOlo);
    cudaGetSymbolAddress((void**)&Qhi,   g_Qhi);
    cudaGetSymbolAddress((void**)&Qlo,   g_Qlo);
    cudaGetSymbolAddress((void**)&Vhi,   g_Vhi);
    cudaGetSymbolAddress((void**)&Vlo,   g_Vlo);
    cudaGetSymbolAddress((void**)&KPhi,  g_KPhi);
    cudaGetSymbolAddress((void**)&KPlo,  g_KPlo);
    cudaGetSymbolAddress((void**)&OThi,  g_OThi);
    cudaGetSymbolAddress((void**)&OTlo,  g_OTlo);

    const int M  = NB * NL;
    const int Mr = NB * NG;
    const int N  = D_MODEL, K = D_MODEL;

    cudaFuncSetAttribute(gemm_mma_kernel,
                         cudaFuncAttributeMaxDynamicSharedMemorySize, GEMM_SMEM);
    cudaFuncSetAttribute(attn_mma_kernel,
                         cudaFuncAttributeMaxDynamicSharedMemorySize, ATT_SMEM);

    static cudaStream_t s1 = nullptr, s2 = nullptr, s3 = nullptr;
    static cudaEvent_t ev0 = nullptr, evQ = nullptr, evV = nullptr,
                       evR = nullptr, evWo = nullptr;
    if (!s1) {
        cudaStreamCreateWithFlags(&s1, cudaStreamNonBlocking);
        cudaStreamCreateWithFlags(&s2, cudaStreamNonBlocking);
        cudaStreamCreateWithFlags(&s3, cudaStreamNonBlocking);
        cudaEventCreateWithFlags(&ev0, cudaEventDisableTiming);
        cudaEventCreateWithFlags(&evQ, cudaEventDisableTiming);
        cudaEventCreateWithFlags(&evV, cudaEventDisableTiming);
        cudaEventCreateWithFlags(&evR, cudaEventDisableTiming);
        cudaEventCreateWithFlags(&evWo, cudaEventDisableTiming);
    }

    dim3 cw(32, 32);
    dim3 gBig(N / 128, M / 128);
    dim3 gRtr(N / 128, Mr / 128);
    const int nBig = M * K, nRtr = Mr * K;

    cudaEventRecord(ev0, 0);
    cudaStreamWaitEvent(s1, ev0, 0);
    cudaStreamWaitEvent(s2, ev0, 0);
    cudaStreamWaitEvent(s3, ev0, 0);

    // ---- main stream: critical path (K chain) ----
    conv_hilo_kernel<<<nBig / 1024, 256>>>(keys, KAhi, KAlo, nBig);
    conv_wt_kernel<<<cw, 256>>>(Wk, WKhi, WKlo);
    gemm_mma_kernel<<<gBig, 256, GEMM_SMEM>>>(KAhi, KAlo, WKhi, WKlo, Kp, nullptr, nullptr, nullptr, M, N, K);

    // ---- s1: Q chain ----
    conv_hilo_kernel<<<nBig / 1024, 256, 0, s1>>>(queries, QAhi, QAlo, nBig);
    conv_wt_kernel<<<cw, 256, 0, s1>>>(Wq, WQhi, WQlo);
    gemm_mma_kernel<<<gBig, 256, GEMM_SMEM, s1>>>(QAhi, QAlo, WQhi, WQlo, nullptr, nullptr, Qhi, Qlo, M, N, K);
    cudaEventRecord(evQ, s1);

    // ---- s2: V chain ----
    conv_hilo_kernel<<<nBig / 1024, 256, 0, s2>>>(values, VAhi, VAlo, nBig);
    conv_wt_kernel<<<cw, 256, 0, s2>>>(Wv, WVhi, WVlo);
    gemm_mma_kernel<<<gBig, 256, GEMM_SMEM, s2>>>(VAhi, VAlo, WVhi, WVlo, nullptr, nullptr, Vhi, Vlo, M, N, K);
    cudaEventRecord(evV, s2);

    // ---- s3: router chain + Wo conversion ----
    conv_hilo_kernel<<<nRtr / 1024, 256, 0, s3>>>(routers, RAhi, RAlo, nRtr);
    conv_wt_kernel<<<cw, 256, 0, s3>>>(Wlq, WLQhi, WLQlo);
    gemm_mma_kernel<<<gRtr, 256, GEMM_SMEM, s3>>>(RAhi, RAlo, WLQhi, WLQlo, RQ, nullptr, nullptr, nullptr, Mr, N, K);
    conv_wt_kernel<<<cw, 256, 0, s3>>>(Wlk, WLKhi, WLKlo);
    gemm_mma_kernel<<<gRtr, 256, GEMM_SMEM, s3>>>(RAhi, RAlo, WLKhi, WLKlo, RK, nullptr, nullptr, nullptr, Mr, N, K);
    wep_kernel<<<NB * NH, 256, 0, s3>>>(RQ, RK, WEP);
    cudaEventRecord(evR, s3);
    conv_wt_kernel<<<cw, 256, 0, s3>>>(Wo, WOhi, WOlo);
    cudaEventRecord(evWo, s3);

    // ---- main: kprime (needs K + WEP) ----
    cudaStreamWaitEvent(0, evR, 0);
    dim3 gKP(NL / 64, NB * NH);
    kprime_kernel<<<gKP, 256>>>(Kp, WEP, KPhi, KPlo);

    // ---- main: attention (needs Q, V, KP) ----
    cudaStreamWaitEvent(0, evQ, 0);
    cudaStreamWaitEvent(0, evV, 0);
    dim3 gAtt(NL / 256, NB * NH);   // (4, 128)
    attn_mma_kernel<<<gAtt, 256, ATT_SMEM>>>(Qhi, Qlo, KPhi, KPlo, Vhi, Vlo, OThi, OTlo);

    // ---- main: final GEMM with bias ----
    cudaStreamWaitEvent(0, evWo, 0);
    gemm_mma_kernel<<<gBig, 256, GEMM_SMEM>>>(OThi, OTlo, WOhi, WOlo, out, bo, nullptr, nullptr, M, N, K);
}

// round 16
// speedup vs baseline: 1.0362x; 1.0362x over previous
#include <cuda_runtime.h>
#include <cuda_bf16.h>
#include <cstdint>

// ============================================================================
// Shapes (fixed): B=8, L=S=1024, G=64, D=1024, H=16, d_head=64
// compute_103 PTX: no tcgen05; mma.sync bf16 with hi/lo split precision.
// This round: attention -> 2 CTAs/SM (96KB smem, <=128 regs) to overlap
// softmax scalar sections of one CTA with MMAs of the other.
// GEMM + dataflow are the exact round-6 (930.7us) configuration.
// ============================================================================

#define D_MODEL 1024
#define NB 8
#define NL 1024
#define NG 64
#define NH 16
#define DH 64

typedef __nv_bfloat16 bf16;

// -------------------- scratch (device globals; no allocation) ---------------
__device__ float g_K  [NB * NL * D_MODEL];
__device__ float g_RQ [NB * NG * D_MODEL];
__device__ float g_RK [NB * NG * D_MODEL];
__device__ float g_WEP[NB * NH * DH * DH];
__device__ bf16 g_QAhi[NB * NL * D_MODEL];
__device__ bf16 g_QAlo[NB * NL * D_MODEL];
__device__ bf16 g_KAhi[NB * NL * D_MODEL];
__device__ bf16 g_KAlo[NB * NL * D_MODEL];
__device__ bf16 g_VAhi[NB * NL * D_MODEL];
__device__ bf16 g_VAlo[NB * NL * D_MODEL];
__device__ bf16 g_RAhi[NB * NG * D_MODEL];
__device__ bf16 g_RAlo[NB * NG * D_MODEL];
__device__ bf16 g_WQhi[D_MODEL * D_MODEL];
__device__ bf16 g_WQlo[D_MODEL * D_MODEL];
__device__ bf16 g_WKhi[D_MODEL * D_MODEL];
__device__ bf16 g_WKlo[D_MODEL * D_MODEL];
__device__ bf16 g_WVhi[D_MODEL * D_MODEL];
__device__ bf16 g_WVlo[D_MODEL * D_MODEL];
__device__ bf16 g_WLQhi[D_MODEL * D_MODEL];
__device__ bf16 g_WLQlo[D_MODEL * D_MODEL];
__device__ bf16 g_WLKhi[D_MODEL * D_MODEL];
__device__ bf16 g_WLKlo[D_MODEL * D_MODEL];
__device__ bf16 g_WOhi[D_MODEL * D_MODEL];
__device__ bf16 g_WOlo[D_MODEL * D_MODEL];
__device__ bf16 g_Qhi[NB * NL * D_MODEL];
__device__ bf16 g_Qlo[NB * NL * D_MODEL];
__device__ bf16 g_Vhi[NB * NL * D_MODEL];
__device__ bf16 g_Vlo[NB * NL * D_MODEL];
__device__ bf16 g_KPhi[NB * NH * NL * DH];
__device__ bf16 g_KPlo[NB * NH * NL * DH];
__device__ bf16 g_OThi[NB * NL * D_MODEL];
__device__ bf16 g_OTlo[NB * NL * D_MODEL];

// ============================================================================
// PTX helpers
// ============================================================================
__device__ __forceinline__ uint32_t smem_u32(const void* p) {
    uint32_t a;
    asm("{ .reg .u64 t; cvta.to.shared.u64 t, %1; cvt.u32.u64 %0, t; }" : "=r"(a) : "l"(p));
    return a;
}
#define CP_ASYNC16(dst, src) \
    asm volatile("cp.async.cg.shared.global [%0], [%1], 16;" :: "r"(dst), "l"(src))
#define CP_COMMIT() asm volatile("cp.async.commit_group;" ::: "memory")
#define CP_WAIT(n)  asm volatile("cp.async.wait_group %0;" :: "n"(n) : "memory")

__device__ __forceinline__ void ldmx4(uint32_t* r, uint32_t addr) {
    asm volatile("ldmatrix.sync.aligned.m8n8.x4.shared.b16 {%0,%1,%2,%3}, [%4];"
                 : "=r"(r[0]), "=r"(r[1]), "=r"(r[2]), "=r"(r[3]) : "r"(addr));
}
__device__ __forceinline__ void ldmx4t(uint32_t* r, uint32_t addr) {
    asm volatile("ldmatrix.sync.aligned.m8n8.x4.trans.shared.b16 {%0,%1,%2,%3}, [%4];"
                 : "=r"(r[0]), "=r"(r[1]), "=r"(r[2]), "=r"(r[3]) : "r"(addr));
}
__device__ __forceinline__ void mma_bf16(float* c, const uint32_t* a, const uint32_t* b) {
    asm volatile(
        "mma.sync.aligned.m16n8k16.row.col.f32.bf16.bf16.f32 "
        "{%0,%1,%2,%3}, {%4,%5,%6,%7}, {%8,%9}, {%0,%1,%2,%3};"
        : "+f"(c[0]), "+f"(c[1]), "+f"(c[2]), "+f"(c[3])
        : "r"(a[0]), "r"(a[1]), "r"(a[2]), "r"(a[3]), "r"(b[0]), "r"(b[1]));
}
__device__ __forceinline__ uint32_t pack_bf16(float lo, float hi) {
    __nv_bfloat162 p = __floats2bfloat162_rn(lo, hi);
    return *(uint32_t*)&p;
}
__device__ __forceinline__ void split_pack(float x, float y, uint32_t& hi, uint32_t& lo) {
    bf16 hx = __float2bfloat16_rn(x), hy = __float2bfloat16_rn(y);
    hi = pack_bf16(__bfloat162float(hx), __bfloat162float(hy));
    __nv_bfloat162 hp; *(uint32_t*)&hp = hi;
    lo = pack_bf16(x - __bfloat162float(hp.x), y - __bfloat162float(hp.y));
}

// ============================================================================
// Conversion kernels
// ============================================================================
__global__ __launch_bounds__(256)
void conv_hilo_kernel(const float* __restrict__ in, bf16* __restrict__ hi,
                      bf16* __restrict__ lo, int n)
{
    int i = (blockIdx.x * 256 + threadIdx.x) * 4;
    if (i >= n) return;
    float4 v = *(const float4*)(in + i);
    uint32_t h0, l0, h1, l1;
    split_pack(v.x, v.y, h0, l0);
    split_pack(v.z, v.w, h1, l1);
    *(uint32_t*)(hi + i) = h0; *(uint32_t*)(hi + i + 2) = h1;
    *(uint32_t*)(lo + i) = l0; *(uint32_t*)(lo + i + 2) = l1;
}

__global__ __launch_bounds__(256)
void conv_wt_kernel(const float* __restrict__ W, bf16* __restrict__ th,
                    bf16* __restrict__ tl)
{
    __shared__ float t[32][33];
    int bn = blockIdx.x * 32, bk = blockIdx.y * 32;
    int tx = threadIdx.x & 31, ty = threadIdx.x >> 5;
    #pragma unroll
    for (int j = 0; j < 32; j += 8)
        t[ty + j][tx] = W[(size_t)(bk + ty + j) * D_MODEL + bn + tx];
    __syncthreads();
    #pragma unroll
    for (int j = 0; j < 32; j += 8) {
        float v = t[tx][ty + j];
        bf16 h = __float2bfloat16_rn(v);
        size_t o = (size_t)(bn + ty + j) * D_MODEL + bk + tx;
        th[o] = h;
        tl[o] = __float2bfloat16_rn(v - __bfloat162float(h));
    }
}

// ============================================================================
// mma.sync split-bf16 GEMM — exact round-6 (930.7us) configuration.
// ============================================================================
#define ARR_BYTES   16384
#define STAGE_BYTES (4 * ARR_BYTES)
#define GEMM_SMEM   (3 * STAGE_BYTES)

__global__ __launch_bounds__(256, 1)
void gemm_mma_kernel(const bf16* __restrict__ Ahi, const bf16* __restrict__ Alo,
                     const bf16* __restrict__ Bhi, const bf16* __restrict__ Blo,
                     float* __restrict__ Cf, const float* __restrict__ bias,
                     bf16* __restrict__ Chi, bf16* __restrict__ Clo,
                     int M, int N, int K)
{
    extern __shared__ char smem[];
    const uint32_t sbase = smem_u32(smem);
    const int tid  = threadIdx.x;
    const int wid  = tid >> 5, lane = tid & 31;
    const int wm   = wid & 3;
    const int wn   = wid >> 2;
    const int m0   = blockIdx.y * 128;
    const int n0   = blockIdx.x * 128;
    const int nchunks = K >> 6;

    const bf16* srcs[4] = { Ahi + (size_t)m0 * K, Alo + (size_t)m0 * K,
                            Bhi + (size_t)n0 * K, Blo + (size_t)n0 * K };

    auto issue = [&](int c, int s) {
        const uint32_t stb = sbase + s * STAGE_BYTES;
        #pragma unroll
        for (int a = 0; a < 4; a++) {
            const bf16* src = srcs[a] + c * 64;
            const uint32_t ab = stb + a * ARR_BYTES;
            #pragma unroll
            for (int i = 0; i < 4; i++) {
                int u   = tid + i * 256;
                int row = u >> 3, c8 = u & 7;
                uint32_t dst = ab + row * 128 + ((c8 ^ (row & 7)) << 4);
                CP_ASYNC16(dst, src + (size_t)row * K + c8 * 8);
            }
        }
        CP_COMMIT();
    };

    issue(0, 0);
    issue(1, 1);

    float acc[2][8][4] = {};
    const int a_row0 = wm * 32 + (lane & 15);
    const int a_sub  = lane >> 4;
    const int g      = lane >> 3;
    const int b_noff = ((g & 2) << 2) + (lane & 7);
    const int b_sub  = g & 1;

    for (int c = 0; c < nchunks; c++) {
        if (c + 1 < nchunks) CP_WAIT(1);
        else                 CP_WAIT(0);
        __syncthreads();
        if (c + 2 < nchunks) issue(c + 2, (c + 2) % 3);

        const uint32_t stb = sbase + (c % 3) * STAGE_BYTES;
        const uint32_t Ah = stb, Al = stb + ARR_BYTES;
        const uint32_t Bh = stb + 2 * ARR_BYTES, Bl = stb + 3 * ARR_BYTES;

        #pragma unroll
        for (int k16 = 0; k16 < 4; k16++) {
            const int kc = k16 * 2;
            uint32_t ah[2][4], al[2][4], bh[4][4], bl[4][4];
            #pragma unroll
            for (int mi = 0; mi < 2; mi++) {
                int row = a_row0 + mi * 16;
                uint32_t off = row * 128 + (((kc + a_sub) ^ (row & 7)) << 4);
                ldmx4(ah[mi], Ah + off);
                ldmx4(al[mi], Al + off);
            }
            #pragma unroll
            for (int pn = 0; pn < 4; pn++) {
                int n = wn * 64 + pn * 16 + b_noff;
                uint32_t off = n * 128 + (((kc + b_sub) ^ (n & 7)) << 4);
                ldmx4(bh[pn], Bh + off);
                ldmx4(bl[pn], Bl + off);
            }
            #pragma unroll
            for (int mi = 0; mi < 2; mi++)
                #pragma unroll
                for (int ni = 0; ni < 8; ni++) {
                    const uint32_t* bf = &bh[ni >> 1][(ni & 1) * 2];
                    const uint32_t* lf = &bl[ni >> 1][(ni & 1) * 2];
                    mma_bf16(acc[mi][ni], ah[mi], bf);
                    mma_bf16(acc[mi][ni], al[mi], bf);
                    mma_bf16(acc[mi][ni], ah[mi], lf);
                }
        }
    }

    const int tr = lane >> 2, tc = (lane & 3) * 2;
    const int rbase = m0 + wm * 32;
    const int cbase = n0 + wn * 64;
    #pragma unroll
    for (int mi = 0; mi < 2; mi++) {
        #pragma unroll
        for (int ni = 0; ni < 8; ni++) {
            int col = cbase + ni * 8 + tc;
            int r0 = rbase + mi * 16 + tr;
            if (Chi) {
                uint32_t h0, l0, h1, l1;
                split_pack(acc[mi][ni][0], acc[mi][ni][1], h0, l0);
                split_pack(acc[mi][ni][2], acc[mi][ni][3], h1, l1);
                *(uint32_t*)(Chi + (size_t)r0 * N + col)       = h0;
                *(uint32_t*)(Clo + (size_t)r0 * N + col)       = l0;
                *(uint32_t*)(Chi + (size_t)(r0 + 8) * N + col) = h1;
                *(uint32_t*)(Clo + (size_t)(r0 + 8) * N + col) = l1;
            } else {
                float bx = 0.f, by = 0.f;
                if (bias) { float2 bv = *(const float2*)(bias + col); bx = bv.x; by = bv.y; }
                float2 v0; v0.x = acc[mi][ni][0] + bx; v0.y = acc[mi][ni][1] + by;
                *(float2*)(Cf + (size_t)r0 * N + col) = v0;
                float2 v1; v1.x = acc[mi][ni][2] + bx; v1.y = acc[mi][ni][3] + by;
                *(float2*)(Cf + (size_t)(r0 + 8) * N + col) = v1;
            }
        }
    }
}

// ============================================================================
// W_ep[bh][d][e] = (1/8) * sum_g rq[b,g,h*64+d] * rk[b,g,h*64+e]
// ============================================================================
#define AP 68

__global__ __launch_bounds__(256)
void wep_kernel(const float* __restrict__ RQ, const float* __restrict__ RK,
                float* __restrict__ WEP)
{
    __shared__ float sA[64 * AP];
    __shared__ float sB[64 * AP];
    const int tid = threadIdx.x;
    const int bh  = blockIdx.x;
    const int b   = bh >> 4, h = bh & 15;
    const int ldr = tid >> 2;
    const int lds = (tid & 3) * 16;
    const float* rqg = RQ + (size_t)(b * NG) * D_MODEL + h * DH;
    const float* rkg = RK + (size_t)(b * NG) * D_MODEL + h * DH;
    #pragma unroll
    for (int s = 0; s < 4; s++) {
        *(float4*)&sA[ldr * AP + lds + s * 4] =
            *(const float4*)(rqg + (size_t)ldr * D_MODEL + lds + s * 4);
        *(float4*)&sB[ldr * AP + lds + s * 4] =
            *(const float4*)(rkg + (size_t)ldr * D_MODEL + lds + s * 4);
    }
    __syncthreads();
    const int tRow = (tid >> 4) * 4;
    const int tCol = (tid & 15) * 4;
    float acc[4][4] = {};
    #pragma unroll 8
    for (int g = 0; g < 64; g++) {
        float rm[4], rn[4];
        #pragma unroll
        for (int i = 0; i < 4; i++) rm[i] = sA[g * AP + tRow + i];
        #pragma unroll
        for (int j = 0; j < 4; j++) rn[j] = sB[g * AP + tCol + j];
        #pragma unroll
        for (int i = 0; i < 4; i++)
            #pragma unroll
            for (int j = 0; j < 4; j++)
                acc[i][j] += rm[i] * rn[j];
    }
    float* wout = WEP + (size_t)bh * (DH * DH);
    #pragma unroll
    for (int i = 0; i < 4; i++)
        #pragma unroll
        for (int j = 0; j < 4; j++)
            wout[(tRow + i) * DH + tCol + j] = acc[i][j] * 0.125f;
}

// ============================================================================
// K'[bh][s][d] = sum_e K[b][s][h*64+e] * WEP[bh][d][e]  -> hi/lo bf16
// ============================================================================
__global__ __launch_bounds__(256)
void kprime_kernel(const float* __restrict__ Kp, const float* __restrict__ WEP,
                   bf16* __restrict__ KPhi, bf16* __restrict__ KPlo)
{
    __shared__ float sK[64 * AP];
    __shared__ float sW[64 * AP];
    const int tid = threadIdx.x;
    const int st  = blockIdx.x;
    const int bh  = blockIdx.y;
    const int b   = bh >> 4, h = bh & 15;
    const int s0  = st * 64;
    const int ldr = tid >> 2;
    const int lds = (tid & 3) * 16;

    const float* kg = Kp + (size_t)(b * NL + s0) * D_MODEL + h * DH;
    const float* wg = WEP + (size_t)bh * (DH * DH);
    #pragma unroll
    for (int s = 0; s < 4; s++) {
        *(float4*)&sK[ldr * AP + lds + s * 4] =
            *(const float4*)(kg + (size_t)ldr * D_MODEL + lds + s * 4);
        *(float4*)&sW[ldr * AP + lds + s * 4] =
            *(const float4*)(wg + ldr * DH + lds + s * 4);
    }
    __syncthreads();

    const int tRow = (tid >> 4) * 4;
    const int tCol = (tid & 15) * 4;
    float acc[4][4] = {};
    #pragma unroll 8
    for (int e = 0; e < 64; e++) {
        float rm[4], rn[4];
        #pragma unroll
        for (int i = 0; i < 4; i++) rm[i] = sK[(tRow + i) * AP + e];
        #pragma unroll
        for (int j = 0; j < 4; j++) rn[j] = sW[(tCol + j) * AP + e];
        #pragma unroll
        for (int i = 0; i < 4; i++)
            #pragma unroll
            for (int j = 0; j < 4; j++)
                acc[i][j] += rm[i] * rn[j];
    }
    #pragma unroll
    for (int i = 0; i < 4; i++) {
        size_t o = (size_t)(bh * NL + s0 + tRow + i) * DH + tCol;
        uint32_t h0, l0, h1, l1;
        split_pack(acc[i][0], acc[i][1], h0, l0);
        split_pack(acc[i][2], acc[i][3], h1, l1);
        *(uint32_t*)(KPhi + o)     = h0;  *(uint32_t*)(KPlo + o)     = l0;
        *(uint32_t*)(KPhi + o + 2) = h1;  *(uint32_t*)(KPlo + o + 2) = l1;
    }
}

// ============================================================================
// Flash attention: q-tile 128 rows, 8 warps x 16 rows; 2-stage pipeline,
// 96KB smem + <=128 regs => 2 CTAs/SM. P packed on-the-fly in PV loop.
// ============================================================================
#define ATT_STAGE 32768
#define ATT_SMEM  (2 * ATT_STAGE + 32768)   // 98304

__global__ __launch_bounds__(256, 2)
void attn_mma_kernel(const bf16* __restrict__ Qhi, const bf16* __restrict__ Qlo,
                     const bf16* __restrict__ KPhi, const bf16* __restrict__ KPlo,
                     const bf16* __restrict__ Vhi, const bf16* __restrict__ Vlo,
                     bf16* __restrict__ OThi, bf16* __restrict__ OTlo)
{
    extern __shared__ char smem[];
    const uint32_t sb = smem_u32(smem);
    const uint32_t QH = sb + 2 * ATT_STAGE, QL = QH + 16384;
    const int tid = threadIdx.x;
    const int wid = tid >> 5, lane = tid & 31;
    const int mt = blockIdx.x;
    const int bh = blockIdx.y;
    const int b = bh >> 4, h = bh & 15;
    const int l0 = mt * 128;

    {
        const bf16* qh = Qhi + (size_t)(b * NL + l0) * D_MODEL + h * DH;
        const bf16* ql = Qlo + (size_t)(b * NL + l0) * D_MODEL + h * DH;
        #pragma unroll
        for (int i = 0; i < 4; i++) {
            int u = tid + i * 256;
            int row = u >> 3, c8 = u & 7;
            uint32_t sw = row * 128 + ((c8 ^ (row & 7)) << 4);
            CP_ASYNC16(QH + sw, qh + (size_t)row * D_MODEL + c8 * 8);
            CP_ASYNC16(QL + sw, ql + (size_t)row * D_MODEL + c8 * 8);
        }
        CP_COMMIT();
    }

    const bf16* kph = KPhi + (size_t)bh * NL * DH;
    const bf16* kpl = KPlo + (size_t)bh * NL * DH;
    const bf16* vh  = Vhi + (size_t)b * NL * D_MODEL + h * DH;
    const bf16* vl  = Vlo + (size_t)b * NL * D_MODEL + h * DH;

    auto issue_stage = [&](int nc, int s) {
        const uint32_t stb = sb + s * ATT_STAGE;
        #pragma unroll
        for (int i = 0; i < 2; i++) {
            int u = tid + i * 256;
            int row = u >> 3, c8 = u & 7;
            uint32_t sw = row * 128 + ((c8 ^ (row & 7)) << 4);
            CP_ASYNC16(stb + sw,         kph + (size_t)(nc * 64 + row) * DH + c8 * 8);
            CP_ASYNC16(stb + 8192 + sw,  kpl + (size_t)(nc * 64 + row) * DH + c8 * 8);
            CP_ASYNC16(stb + 16384 + sw, vh + (size_t)(nc * 64 + row) * D_MODEL + c8 * 8);
            CP_ASYNC16(stb + 24576 + sw, vl + (size_t)(nc * 64 + row) * D_MODEL + c8 * 8);
        }
        CP_COMMIT();
    };

    issue_stage(0, 0);
    CP_WAIT(0);          // Q + stage0 complete
    __syncthreads();

    uint32_t qh[4][4], ql[4][4];
    const int r0 = wid * 16;
    const int frow = r0 + (lane & 15);
    const int fsub = lane >> 4;
    #pragma unroll
    for (int kk = 0; kk < 4; kk++) {
        uint32_t off = frow * 128 + (((kk * 2 + fsub) ^ (frow & 7)) << 4);
        ldmx4(qh[kk], QH + off);
        ldmx4(ql[kk], QL + off);
    }

    const int g      = lane >> 3;
    const int b_noff = ((g & 2) << 2) + (lane & 7);
    const int b_sub  = g & 1;

    float mM[2] = { -1e30f, -1e30f }, lS[2] = { 0.f, 0.f };
    float o[8][4] = {};

    for (int nc = 0; nc < 16; nc++) {
        if (nc > 0) { CP_WAIT(0); __syncthreads(); }
        if (nc + 1 < 16) issue_stage(nc + 1, (nc + 1) & 1);   // after barrier: safe reuse
        const uint32_t stb = sb + (nc & 1) * ATT_STAGE;

        // ---- scores (3-term split)
        float sc[8][4] = {};
        #pragma unroll
        for (int kk = 0; kk < 4; kk++) {
            uint32_t kb[4][4], klo[4][4];
            #pragma unroll
            for (int ng = 0; ng < 4; ng++) {
                int nr = ng * 16 + b_noff;
                uint32_t off = nr * 128 + (((kk * 2 + b_sub) ^ (nr & 7)) << 4);
                ldmx4(kb[ng], stb + off);
                ldmx4(klo[ng], stb + 8192 + off);
            }
            #pragma unroll
            for (int ng = 0; ng < 4; ng++)
                #pragma unroll
                for (int hf = 0; hf < 2; hf++) {
                    float* a = sc[ng * 2 + hf];
                    mma_bf16(a, qh[kk], &kb[ng][hf * 2]);
                    mma_bf16(a, ql[kk], &kb[ng][hf * 2]);
                    mma_bf16(a, qh[kk], &klo[ng][hf * 2]);
                }
        }

        // ---- online softmax; store p back into sc (no persistent pack arrays)
        float rmax0 = -1e30f, rmax1 = -1e30f;
        #pragma unroll
        for (int t = 0; t < 8; t++) {
            rmax0 = fmaxf(rmax0, fmaxf(sc[t][0], sc[t][1]));
            rmax1 = fmaxf(rmax1, fmaxf(sc[t][2], sc[t][3]));
        }
        #pragma unroll
        for (int off = 1; off <= 2; off <<= 1) {
            rmax0 = fmaxf(rmax0, __shfl_xor_sync(0xffffffffu, rmax0, off));
            rmax1 = fmaxf(rmax1, __shfl_xor_sync(0xffffffffu, rmax1, off));
        }
        float nM0 = fmaxf(mM[0], rmax0), nM1 = fmaxf(mM[1], rmax1);
        float cor0 = __expf(mM[0] - nM0), cor1 = __expf(mM[1] - nM1);
        mM[0] = nM0; mM[1] = nM1;

        float ps0 = 0.f, ps1 = 0.f;
        #pragma unroll
        for (int t = 0; t < 8; t++) {
            sc[t][0] = __expf(sc[t][0] - nM0);
            sc[t][1] = __expf(sc[t][1] - nM0);
            sc[t][2] = __expf(sc[t][2] - nM1);
            sc[t][3] = __expf(sc[t][3] - nM1);
            ps0 += sc[t][0] + sc[t][1];
            ps1 += sc[t][2] + sc[t][3];
        }
        #pragma unroll
        for (int off = 1; off <= 2; off <<= 1) {
            ps0 += __shfl_xor_sync(0xffffffffu, ps0, off);
            ps1 += __shfl_xor_sync(0xffffffffu, ps1, off);
        }
        lS[0] = lS[0] * cor0 + ps0;
        lS[1] = lS[1] * cor1 + ps1;
        #pragma unroll
        for (int t = 0; t < 8; t++) {
            o[t][0] *= cor0; o[t][1] *= cor0;
            o[t][2] *= cor1; o[t][3] *= cor1;
        }

        // ---- PV (3-term); pack P fragments on the fly
        #pragma unroll
        for (int kk = 0; kk < 4; kk++) {
            uint32_t vb[4][4], vlo[4][4];
            #pragma unroll
            for (int ng = 0; ng < 4; ng++) {
                int srow = kk * 16 + (lane & 7) + 8 * ((lane >> 3) & 1);
                uint32_t c8 = 2 * ng + (lane >> 4);
                uint32_t off = srow * 128 + ((c8 ^ (srow & 7)) << 4);
                ldmx4t(vb[ng], stb + 16384 + off);
                ldmx4t(vlo[ng], stb + 24576 + off);
            }
            uint32_t pa[4], pal[4];
            split_pack(sc[2 * kk][0],     sc[2 * kk][1],     pa[0], pal[0]);
            split_pack(sc[2 * kk][2],     sc[2 * kk][3],     pa[1], pal[1]);
            split_pack(sc[2 * kk + 1][0], sc[2 * kk + 1][1], pa[2], pal[2]);
            split_pack(sc[2 * kk + 1][2], sc[2 * kk + 1][3], pa[3], pal[3]);
            #pragma unroll
            for (int ng = 0; ng < 4; ng++)
                #pragma unroll
                for (int hf = 0; hf < 2; hf++) {
                    float* c = o[ng * 2 + hf];
                    mma_bf16(c, pa, &vb[ng][hf * 2]);
                    mma_bf16(c, pal, &vb[ng][hf * 2]);
                    mma_bf16(c, pa, &vlo[ng][hf * 2]);
                }
        }
    }
    __syncthreads();

    float inv0 = 1.0f / lS[0], inv1 = 1.0f / lS[1];
    float* sOT = (float*)smem;
    const int orow = lane >> 2, ocol = (lane & 3) * 2;
    #pragma unroll
    for (int t = 0; t < 8; t++) {
        int d = t * 8 + ocol;
        sOT[(d + 0) * 132 + r0 + orow]     = o[t][0] * inv0;
        sOT[(d + 1) * 132 + r0 + orow]     = o[t][1] * inv0;
        sOT[(d + 0) * 132 + r0 + orow + 8] = o[t][2] * inv1;
        sOT[(d + 1) * 132 + r0 + orow + 8] = o[t][3] * inv1;
    }
    __syncthreads();

    {
        const int d = tid >> 2;
        const int mseg = (tid & 3) * 32;
        size_t gro = (size_t)(b * NL + h * DH + d) * NL + l0 + mseg;
        #pragma unroll
        for (int j = 0; j < 32; j += 2) {
            float f0 = sOT[d * 132 + mseg + j];
            float f1 = sOT[d * 132 + mseg + j + 1];
            uint32_t hp, lp;
            split_pack(f0, f1, hp, lp);
            *(uint32_t*)(OThi + gro + j) = hp;
            *(uint32_t*)(OTlo + gro + j) = lp;
        }
    }
}

// ============================================================================
// Launch — multi-stream fork/join (graph-capture-safe), round-6 topology
// ============================================================================
extern "C" void kernel_launch(void* const* d_in, const int* in_sizes, int n_in,
                              void* d_out, int out_size)
{
    const float* queries = (const float*)d_in[0];
    const float* keys    = (const float*)d_in[1];
    const float* values  = (const float*)d_in[2];
    const float* routers = (const float*)d_in[3];
    const float* Wq      = (const float*)d_in[4];
    const float* Wk      = (const float*)d_in[5];
    const float* Wv      = (const float*)d_in[6];
    const float* Wlq     = (const float*)d_in[7];
    const float* Wlk     = (const float*)d_in[8];
    const float* Wo      = (const float*)d_in[9];
    const float* bo      = (const float*)d_in[10];
    float* out           = (float*)d_out;

    float *Kp, *RQ, *RK, *WEP;
    bf16 *QAhi, *QAlo, *KAhi, *KAlo, *VAhi, *VAlo, *RAhi, *RAlo;
    bf16 *WQhi, *WQlo, *WKhi, *WKlo, *WVhi, *WVlo, *WLQhi, *WLQlo, *WLKhi, *WLKlo, *WOhi, *WOlo;
    bf16 *Qhi, *Qlo, *Vhi, *Vlo, *KPhi, *KPlo, *OThi, *OTlo;
    cudaGetSymbolAddress((void**)&Kp,    g_K);
    cudaGetSymbolAddress((void**)&RQ,    g_RQ);
    cudaGetSymbolAddress((void**)&RK,    g_RK);
    cudaGetSymbolAddress((void**)&WEP,   g_WEP);
    cudaGetSymbolAddress((void**)&QAhi,  g_QAhi);
    cudaGetSymbolAddress((void**)&QAlo,  g_QAlo);
    cudaGetSymbolAddress((void**)&KAhi,  g_KAhi);
    cudaGetSymbolAddress((void**)&KAlo,  g_KAlo);
    cudaGetSymbolAddress((void**)&VAhi,  g_VAhi);
    cudaGetSymbolAddress((void**)&VAlo,  g_VAlo);
    cudaGetSymbolAddress((void**)&RAhi,  g_RAhi);
    cudaGetSymbolAddress((void**)&RAlo,  g_RAlo);
    cudaGetSymbolAddress((void**)&WQhi,  g_WQhi);
    cudaGetSymbolAddress((void**)&WQlo,  g_WQlo);
    cudaGetSymbolAddress((void**)&WKhi,  g_WKhi);
    cudaGetSymbolAddress((void**)&WKlo,  g_WKlo);
    cudaGetSymbolAddress((void**)&WVhi,  g_WVhi);
    cudaGetSymbolAddress((void**)&WVlo,  g_WVlo);
    cudaGetSymbolAddress((void**)&WLQhi, g_WLQhi);
    cudaGetSymbolAddress((void**)&WLQlo, g_WLQlo);
    cudaGetSymbolAddress((void**)&WLKhi, g_WLKhi);
    cudaGetSymbolAddress((void**)&WLKlo, g_WLKlo);
    cudaGetSymbolAddress((void**)&WOhi,  g_WOhi);
    cudaGetSymbolAddress((void**)&WOlo,  g_WOlo);
    cudaGetSymbolAddress((void**)&Qhi,   g_Qhi);
    cudaGetSymbolAddress((void**)&Qlo,   g_Qlo);
    cudaGetSymbolAddress((void**)&Vhi,   g_Vhi);
    cudaGetSymbolAddress((void**)&Vlo,   g_Vlo);
    cudaGetSymbolAddress((void**)&KPhi,  g_KPhi);
    cudaGetSymbolAddress((void**)&KPlo,  g_KPlo);
    cudaGetSymbolAddress((void**)&OThi,  g_OThi);
    cudaGetSymbolAddress((void**)&OTlo,  g_OTlo);

    const int M  = NB * NL;
    const int Mr = NB * NG;
    const int N  = D_MODEL, K = D_MODEL;

    cudaFuncSetAttribute(gemm_mma_kernel,
                         cudaFuncAttributeMaxDynamicSharedMemorySize, GEMM_SMEM);
    cudaFuncSetAttribute(attn_mma_kernel,
                         cudaFuncAttributeMaxDynamicSharedMemorySize, ATT_SMEM);

    static cudaStream_t s1 = nullptr, s2 = nullptr, s3 = nullptr;
    static cudaEvent_t ev0 = nullptr, evQ = nullptr, evV = nullptr,
                       evR = nullptr, evWo = nullptr;
    if (!s1) {
        cudaStreamCreateWithFlags(&s1, cudaStreamNonBlocking);
        cudaStreamCreateWithFlags(&s2, cudaStreamNonBlocking);
        cudaStreamCreateWithFlags(&s3, cudaStreamNonBlocking);
        cudaEventCreateWithFlags(&ev0, cudaEventDisableTiming);
        cudaEventCreateWithFlags(&evQ, cudaEventDisableTiming);
        cudaEventCreateWithFlags(&evV, cudaEventDisableTiming);
        cudaEventCreateWithFlags(&evR, cudaEventDisableTiming);
        cudaEventCreateWithFlags(&evWo, cudaEventDisableTiming);
    }

    dim3 cw(32, 32);
    dim3 gBig(N / 128, M / 128);
    dim3 gRtr(N / 128, Mr / 128);
    const int nBig = M * K, nRtr = Mr * K;

    cudaEventRecord(ev0, 0);
    cudaStreamWaitEvent(s1, ev0, 0);
    cudaStreamWaitEvent(s2, ev0, 0);
    cudaStreamWaitEvent(s3, ev0, 0);

    // ---- main stream: critical path (K chain) ----
    conv_hilo_kernel<<<nBig / 1024, 256>>>(keys, KAhi, KAlo, nBig);
    conv_wt_kernel<<<cw, 256>>>(Wk, WKhi, WKlo);
    gemm_mma_kernel<<<gBig, 256, GEMM_SMEM>>>(KAhi, KAlo, WKhi, WKlo, Kp, nullptr, nullptr, nullptr, M, N, K);

    // ---- s1: Q chain ----
    conv_hilo_kernel<<<nBig / 1024, 256, 0, s1>>>(queries, QAhi, QAlo, nBig);
    conv_wt_kernel<<<cw, 256, 0, s1>>>(Wq, WQhi, WQlo);
    gemm_mma_kernel<<<gBig, 256, GEMM_SMEM, s1>>>(QAhi, QAlo, WQhi, WQlo, nullptr, nullptr, Qhi, Qlo, M, N, K);
    cudaEventRecord(evQ, s1);

    // ---- s2: V chain ----
    conv_hilo_kernel<<<nBig / 1024, 256, 0, s2>>>(values, VAhi, VAlo, nBig);
    conv_wt_kernel<<<cw, 256, 0, s2>>>(Wv, WVhi, WVlo);
    gemm_mma_kernel<<<gBig, 256, GEMM_SMEM, s2>>>(VAhi, VAlo, WVhi, WVlo, nullptr, nullptr, Vhi, Vlo, M, N, K);
    cudaEventRecord(evV, s2);

    // ---- s3: router chain + Wo conversion ----
    conv_hilo_kernel<<<nRtr / 1024, 256, 0, s3>>>(routers, RAhi, RAlo, nRtr);
    conv_wt_kernel<<<cw, 256, 0, s3>>>(Wlq, WLQhi, WLQlo);
    gemm_mma_kernel<<<gRtr, 256, GEMM_SMEM, s3>>>(RAhi, RAlo, WLQhi, WLQlo, RQ, nullptr, nullptr, nullptr, Mr, N, K);
    conv_wt_kernel<<<cw, 256, 0, s3>>>(Wlk, WLKhi, WLKlo);
    gemm_mma_kernel<<<gRtr, 256, GEMM_SMEM, s3>>>(RAhi, RAlo, WLKhi, WLKlo, RK, nullptr, nullptr, nullptr, Mr, N, K);
    wep_kernel<<<NB * NH, 256, 0, s3>>>(RQ, RK, WEP);
    cudaEventRecord(evR, s3);
    conv_wt_kernel<<<cw, 256, 0, s3>>>(Wo, WOhi, WOlo);
    cudaEventRecord(evWo, s3);

    // ---- main: kprime (needs K + WEP) ----
    cudaStreamWaitEvent(0, evR, 0);
    dim3 gKP(NL / 64, NB * NH);
    kprime_kernel<<<gKP, 256>>>(Kp, WEP, KPhi, KPlo);

    // ---- main: attention (needs Q, V, KP) ----
    cudaStreamWaitEvent(0, evQ, 0);
    cudaStreamWaitEvent(0, evV, 0);
    dim3 gAtt(NL / 128, NB * NH);
    attn_mma_kernel<<<gAtt, 256, ATT_SMEM>>>(Qhi, Qlo, KPhi, KPlo, Vhi, Vlo, OThi, OTlo);

    // ---- main: final GEMM with bias ----
    cudaStreamWaitEvent(0, evWo, 0);
    gemm_mma_kernel<<<gBig, 256, GEMM_SMEM>>>(OThi, OTlo, WOhi, WOlo, out, bo, nullptr, nullptr, M, N, K);
}

// round 17
// speedup vs baseline: 1.0370x; 1.0008x over previous
#include <cuda_runtime.h>
#include <cuda_bf16.h>
#include <cstdint>

// ============================================================================
// Shapes (fixed): B=8, L=S=1024, G=64, D=1024, H=16, d_head=64
// compute_103 PTX: no tcgen05; mma.sync bf16 with hi/lo split precision.
// This round: GEMM fragment double-buffering — overlap LDSM of k16+1 with
// HMMAs of k16 to remove the load/MMA phase alternation (issue was 16.5%).
// Attention (2 CTAs/SM) and dataflow identical to the 923.8us round.
// ============================================================================

#define D_MODEL 1024
#define NB 8
#define NL 1024
#define NG 64
#define NH 16
#define DH 64

typedef __nv_bfloat16 bf16;

// -------------------- scratch (device globals; no allocation) ---------------
__device__ float g_K  [NB * NL * D_MODEL];
__device__ float g_RQ [NB * NG * D_MODEL];
__device__ float g_RK [NB * NG * D_MODEL];
__device__ float g_WEP[NB * NH * DH * DH];
__device__ bf16 g_QAhi[NB * NL * D_MODEL];
__device__ bf16 g_QAlo[NB * NL * D_MODEL];
__device__ bf16 g_KAhi[NB * NL * D_MODEL];
__device__ bf16 g_KAlo[NB * NL * D_MODEL];
__device__ bf16 g_VAhi[NB * NL * D_MODEL];
__device__ bf16 g_VAlo[NB * NL * D_MODEL];
__device__ bf16 g_RAhi[NB * NG * D_MODEL];
__device__ bf16 g_RAlo[NB * NG * D_MODEL];
__device__ bf16 g_WQhi[D_MODEL * D_MODEL];
__device__ bf16 g_WQlo[D_MODEL * D_MODEL];
__device__ bf16 g_WKhi[D_MODEL * D_MODEL];
__device__ bf16 g_WKlo[D_MODEL * D_MODEL];
__device__ bf16 g_WVhi[D_MODEL * D_MODEL];
__device__ bf16 g_WVlo[D_MODEL * D_MODEL];
__device__ bf16 g_WLQhi[D_MODEL * D_MODEL];
__device__ bf16 g_WLQlo[D_MODEL * D_MODEL];
__device__ bf16 g_WLKhi[D_MODEL * D_MODEL];
__device__ bf16 g_WLKlo[D_MODEL * D_MODEL];
__device__ bf16 g_WOhi[D_MODEL * D_MODEL];
__device__ bf16 g_WOlo[D_MODEL * D_MODEL];
__device__ bf16 g_Qhi[NB * NL * D_MODEL];
__device__ bf16 g_Qlo[NB * NL * D_MODEL];
__device__ bf16 g_Vhi[NB * NL * D_MODEL];
__device__ bf16 g_Vlo[NB * NL * D_MODEL];
__device__ bf16 g_KPhi[NB * NH * NL * DH];
__device__ bf16 g_KPlo[NB * NH * NL * DH];
__device__ bf16 g_OThi[NB * NL * D_MODEL];
__device__ bf16 g_OTlo[NB * NL * D_MODEL];

// ============================================================================
// PTX helpers
// ============================================================================
__device__ __forceinline__ uint32_t smem_u32(const void* p) {
    uint32_t a;
    asm("{ .reg .u64 t; cvta.to.shared.u64 t, %1; cvt.u32.u64 %0, t; }" : "=r"(a) : "l"(p));
    return a;
}
#define CP_ASYNC16(dst, src) \
    asm volatile("cp.async.cg.shared.global [%0], [%1], 16;" :: "r"(dst), "l"(src))
#define CP_COMMIT() asm volatile("cp.async.commit_group;" ::: "memory")
#define CP_WAIT(n)  asm volatile("cp.async.wait_group %0;" :: "n"(n) : "memory")

__device__ __forceinline__ void ldmx4(uint32_t* r, uint32_t addr) {
    asm volatile("ldmatrix.sync.aligned.m8n8.x4.shared.b16 {%0,%1,%2,%3}, [%4];"
                 : "=r"(r[0]), "=r"(r[1]), "=r"(r[2]), "=r"(r[3]) : "r"(addr));
}
__device__ __forceinline__ void ldmx4t(uint32_t* r, uint32_t addr) {
    asm volatile("ldmatrix.sync.aligned.m8n8.x4.trans.shared.b16 {%0,%1,%2,%3}, [%4];"
                 : "=r"(r[0]), "=r"(r[1]), "=r"(r[2]), "=r"(r[3]) : "r"(addr));
}
__device__ __forceinline__ void mma_bf16(float* c, const uint32_t* a, const uint32_t* b) {
    asm volatile(
        "mma.sync.aligned.m16n8k16.row.col.f32.bf16.bf16.f32 "
        "{%0,%1,%2,%3}, {%4,%5,%6,%7}, {%8,%9}, {%0,%1,%2,%3};"
        : "+f"(c[0]), "+f"(c[1]), "+f"(c[2]), "+f"(c[3])
        : "r"(a[0]), "r"(a[1]), "r"(a[2]), "r"(a[3]), "r"(b[0]), "r"(b[1]));
}
__device__ __forceinline__ uint32_t pack_bf16(float lo, float hi) {
    __nv_bfloat162 p = __floats2bfloat162_rn(lo, hi);
    return *(uint32_t*)&p;
}
__device__ __forceinline__ void split_pack(float x, float y, uint32_t& hi, uint32_t& lo) {
    bf16 hx = __float2bfloat16_rn(x), hy = __float2bfloat16_rn(y);
    hi = pack_bf16(__bfloat162float(hx), __bfloat162float(hy));
    __nv_bfloat162 hp; *(uint32_t*)&hp = hi;
    lo = pack_bf16(x - __bfloat162float(hp.x), y - __bfloat162float(hp.y));
}

// ============================================================================
// Conversion kernels
// ============================================================================
__global__ __launch_bounds__(256)
void conv_hilo_kernel(const float* __restrict__ in, bf16* __restrict__ hi,
                      bf16* __restrict__ lo, int n)
{
    int i = (blockIdx.x * 256 + threadIdx.x) * 4;
    if (i >= n) return;
    float4 v = *(const float4*)(in + i);
    uint32_t h0, l0, h1, l1;
    split_pack(v.x, v.y, h0, l0);
    split_pack(v.z, v.w, h1, l1);
    *(uint32_t*)(hi + i) = h0; *(uint32_t*)(hi + i + 2) = h1;
    *(uint32_t*)(lo + i) = l0; *(uint32_t*)(lo + i + 2) = l1;
}

__global__ __launch_bounds__(256)
void conv_wt_kernel(const float* __restrict__ W, bf16* __restrict__ th,
                    bf16* __restrict__ tl)
{
    __shared__ float t[32][33];
    int bn = blockIdx.x * 32, bk = blockIdx.y * 32;
    int tx = threadIdx.x & 31, ty = threadIdx.x >> 5;
    #pragma unroll
    for (int j = 0; j < 32; j += 8)
        t[ty + j][tx] = W[(size_t)(bk + ty + j) * D_MODEL + bn + tx];
    __syncthreads();
    #pragma unroll
    for (int j = 0; j < 32; j += 8) {
        float v = t[tx][ty + j];
        bf16 h = __float2bfloat16_rn(v);
        size_t o = (size_t)(bn + ty + j) * D_MODEL + bk + tx;
        th[o] = h;
        tl[o] = __float2bfloat16_rn(v - __bfloat162float(h));
    }
}

// ============================================================================
// mma.sync split-bf16 GEMM; round-6 tiling (128x128, 8 warps 4m x 2n, 3-stage)
// + fragment double-buffering: LDSM for k16+1 overlaps HMMAs of k16.
// ============================================================================
#define ARR_BYTES   16384
#define STAGE_BYTES (4 * ARR_BYTES)
#define GEMM_SMEM   (3 * STAGE_BYTES)

__global__ __launch_bounds__(256, 1)
void gemm_mma_kernel(const bf16* __restrict__ Ahi, const bf16* __restrict__ Alo,
                     const bf16* __restrict__ Bhi, const bf16* __restrict__ Blo,
                     float* __restrict__ Cf, const float* __restrict__ bias,
                     bf16* __restrict__ Chi, bf16* __restrict__ Clo,
                     int M, int N, int K)
{
    extern __shared__ char smem[];
    const uint32_t sbase = smem_u32(smem);
    const int tid  = threadIdx.x;
    const int wid  = tid >> 5, lane = tid & 31;
    const int wm   = wid & 3;
    const int wn   = wid >> 2;
    const int m0   = blockIdx.y * 128;
    const int n0   = blockIdx.x * 128;
    const int nchunks = K >> 6;

    const bf16* srcs[4] = { Ahi + (size_t)m0 * K, Alo + (size_t)m0 * K,
                            Bhi + (size_t)n0 * K, Blo + (size_t)n0 * K };

    auto issue = [&](int c, int s) {
        const uint32_t stb = sbase + s * STAGE_BYTES;
        #pragma unroll
        for (int a = 0; a < 4; a++) {
            const bf16* src = srcs[a] + c * 64;
            const uint32_t ab = stb + a * ARR_BYTES;
            #pragma unroll
            for (int i = 0; i < 4; i++) {
                int u   = tid + i * 256;
                int row = u >> 3, c8 = u & 7;
                uint32_t dst = ab + row * 128 + ((c8 ^ (row & 7)) << 4);
                CP_ASYNC16(dst, src + (size_t)row * K + c8 * 8);
            }
        }
        CP_COMMIT();
    };

    issue(0, 0);
    issue(1, 1);

    float acc[2][8][4] = {};
    const int a_row0 = wm * 32 + (lane & 15);
    const int a_sub  = lane >> 4;
    const int g      = lane >> 3;
    const int b_noff = ((g & 2) << 2) + (lane & 7);
    const int b_sub  = g & 1;

    // double-buffered fragments
    uint32_t ah[2][2][4], al[2][2][4], bh[2][4][4], bl[2][4][4];

    for (int c = 0; c < nchunks; c++) {
        if (c + 1 < nchunks) CP_WAIT(1);
        else                 CP_WAIT(0);
        __syncthreads();
        if (c + 2 < nchunks) issue(c + 2, (c + 2) % 3);

        const uint32_t stb = sbase + (c % 3) * STAGE_BYTES;
        const uint32_t Ah = stb, Al = stb + ARR_BYTES;
        const uint32_t Bh = stb + 2 * ARR_BYTES, Bl = stb + 3 * ARR_BYTES;

        // fragment loader for one k16 slice into buffer bf
        auto load_frags = [&](int k16, int bfi) {
            const int kc = k16 * 2;
            #pragma unroll
            for (int mi = 0; mi < 2; mi++) {
                int row = a_row0 + mi * 16;
                uint32_t off = row * 128 + (((kc + a_sub) ^ (row & 7)) << 4);
                ldmx4(ah[bfi][mi], Ah + off);
                ldmx4(al[bfi][mi], Al + off);
            }
            #pragma unroll
            for (int pn = 0; pn < 4; pn++) {
                int n = wn * 64 + pn * 16 + b_noff;
                uint32_t off = n * 128 + (((kc + b_sub) ^ (n & 7)) << 4);
                ldmx4(bh[bfi][pn], Bh + off);
                ldmx4(bl[bfi][pn], Bl + off);
            }
        };

        load_frags(0, 0);
        #pragma unroll
        for (int k16 = 0; k16 < 4; k16++) {
            const int cur = k16 & 1;
            if (k16 < 3) load_frags(k16 + 1, cur ^ 1);   // overlap with MMAs below
            #pragma unroll
            for (int mi = 0; mi < 2; mi++)
                #pragma unroll
                for (int ni = 0; ni < 8; ni++) {
                    const uint32_t* bf = &bh[cur][ni >> 1][(ni & 1) * 2];
                    const uint32_t* lf = &bl[cur][ni >> 1][(ni & 1) * 2];
                    mma_bf16(acc[mi][ni], ah[cur][mi], bf);
                    mma_bf16(acc[mi][ni], al[cur][mi], bf);
                    mma_bf16(acc[mi][ni], ah[cur][mi], lf);
                }
        }
    }

    const int tr = lane >> 2, tc = (lane & 3) * 2;
    const int rbase = m0 + wm * 32;
    const int cbase = n0 + wn * 64;
    #pragma unroll
    for (int mi = 0; mi < 2; mi++) {
        #pragma unroll
        for (int ni = 0; ni < 8; ni++) {
            int col = cbase + ni * 8 + tc;
            int r0 = rbase + mi * 16 + tr;
            if (Chi) {
                uint32_t h0, l0, h1, l1;
                split_pack(acc[mi][ni][0], acc[mi][ni][1], h0, l0);
                split_pack(acc[mi][ni][2], acc[mi][ni][3], h1, l1);
                *(uint32_t*)(Chi + (size_t)r0 * N + col)       = h0;
                *(uint32_t*)(Clo + (size_t)r0 * N + col)       = l0;
                *(uint32_t*)(Chi + (size_t)(r0 + 8) * N + col) = h1;
                *(uint32_t*)(Clo + (size_t)(r0 + 8) * N + col) = l1;
            } else {
                float bx = 0.f, by = 0.f;
                if (bias) { float2 bv = *(const float2*)(bias + col); bx = bv.x; by = bv.y; }
                float2 v0; v0.x = acc[mi][ni][0] + bx; v0.y = acc[mi][ni][1] + by;
                *(float2*)(Cf + (size_t)r0 * N + col) = v0;
                float2 v1; v1.x = acc[mi][ni][2] + bx; v1.y = acc[mi][ni][3] + by;
                *(float2*)(Cf + (size_t)(r0 + 8) * N + col) = v1;
            }
        }
    }
}

// ============================================================================
// W_ep[bh][d][e] = (1/8) * sum_g rq[b,g,h*64+d] * rk[b,g,h*64+e]
// ============================================================================
#define AP 68

__global__ __launch_bounds__(256)
void wep_kernel(const float* __restrict__ RQ, const float* __restrict__ RK,
                float* __restrict__ WEP)
{
    __shared__ float sA[64 * AP];
    __shared__ float sB[64 * AP];
    const int tid = threadIdx.x;
    const int bh  = blockIdx.x;
    const int b   = bh >> 4, h = bh & 15;
    const int ldr = tid >> 2;
    const int lds = (tid & 3) * 16;
    const float* rqg = RQ + (size_t)(b * NG) * D_MODEL + h * DH;
    const float* rkg = RK + (size_t)(b * NG) * D_MODEL + h * DH;
    #pragma unroll
    for (int s = 0; s < 4; s++) {
        *(float4*)&sA[ldr * AP + lds + s * 4] =
            *(const float4*)(rqg + (size_t)ldr * D_MODEL + lds + s * 4);
        *(float4*)&sB[ldr * AP + lds + s * 4] =
            *(const float4*)(rkg + (size_t)ldr * D_MODEL + lds + s * 4);
    }
    __syncthreads();
    const int tRow = (tid >> 4) * 4;
    const int tCol = (tid & 15) * 4;
    float acc[4][4] = {};
    #pragma unroll 8
    for (int g = 0; g < 64; g++) {
        float rm[4], rn[4];
        #pragma unroll
        for (int i = 0; i < 4; i++) rm[i] = sA[g * AP + tRow + i];
        #pragma unroll
        for (int j = 0; j < 4; j++) rn[j] = sB[g * AP + tCol + j];
        #pragma unroll
        for (int i = 0; i < 4; i++)
            #pragma unroll
            for (int j = 0; j < 4; j++)
                acc[i][j] += rm[i] * rn[j];
    }
    float* wout = WEP + (size_t)bh * (DH * DH);
    #pragma unroll
    for (int i = 0; i < 4; i++)
        #pragma unroll
        for (int j = 0; j < 4; j++)
            wout[(tRow + i) * DH + tCol + j] = acc[i][j] * 0.125f;
}

// ============================================================================
// K'[bh][s][d] = sum_e K[b][s][h*64+e] * WEP[bh][d][e]  -> hi/lo bf16
// ============================================================================
__global__ __launch_bounds__(256)
void kprime_kernel(const float* __restrict__ Kp, const float* __restrict__ WEP,
                   bf16* __restrict__ KPhi, bf16* __restrict__ KPlo)
{
    __shared__ float sK[64 * AP];
    __shared__ float sW[64 * AP];
    const int tid = threadIdx.x;
    const int st  = blockIdx.x;
    const int bh  = blockIdx.y;
    const int b   = bh >> 4, h = bh & 15;
    const int s0  = st * 64;
    const int ldr = tid >> 2;
    const int lds = (tid & 3) * 16;

    const float* kg = Kp + (size_t)(b * NL + s0) * D_MODEL + h * DH;
    const float* wg = WEP + (size_t)bh * (DH * DH);
    #pragma unroll
    for (int s = 0; s < 4; s++) {
        *(float4*)&sK[ldr * AP + lds + s * 4] =
            *(const float4*)(kg + (size_t)ldr * D_MODEL + lds + s * 4);
        *(float4*)&sW[ldr * AP + lds + s * 4] =
            *(const float4*)(wg + ldr * DH + lds + s * 4);
    }
    __syncthreads();

    const int tRow = (tid >> 4) * 4;
    const int tCol = (tid & 15) * 4;
    float acc[4][4] = {};
    #pragma unroll 8
    for (int e = 0; e < 64; e++) {
        float rm[4], rn[4];
        #pragma unroll
        for (int i = 0; i < 4; i++) rm[i] = sK[(tRow + i) * AP + e];
        #pragma unroll
        for (int j = 0; j < 4; j++) rn[j] = sW[(tCol + j) * AP + e];
        #pragma unroll
        for (int i = 0; i < 4; i++)
            #pragma unroll
            for (int j = 0; j < 4; j++)
                acc[i][j] += rm[i] * rn[j];
    }
    #pragma unroll
    for (int i = 0; i < 4; i++) {
        size_t o = (size_t)(bh * NL + s0 + tRow + i) * DH + tCol;
        uint32_t h0, l0, h1, l1;
        split_pack(acc[i][0], acc[i][1], h0, l0);
        split_pack(acc[i][2], acc[i][3], h1, l1);
        *(uint32_t*)(KPhi + o)     = h0;  *(uint32_t*)(KPlo + o)     = l0;
        *(uint32_t*)(KPhi + o + 2) = h1;  *(uint32_t*)(KPlo + o + 2) = l1;
    }
}

// ============================================================================
// Flash attention: q-tile 128 rows, 8 warps x 16 rows; 2-stage pipeline,
// 96KB smem + <=128 regs => 2 CTAs/SM. P packed on-the-fly in PV loop.
// (identical to the 923.8us round)
// ============================================================================
#define ATT_STAGE 32768
#define ATT_SMEM  (2 * ATT_STAGE + 32768)   // 98304

__global__ __launch_bounds__(256, 2)
void attn_mma_kernel(const bf16* __restrict__ Qhi, const bf16* __restrict__ Qlo,
                     const bf16* __restrict__ KPhi, const bf16* __restrict__ KPlo,
                     const bf16* __restrict__ Vhi, const bf16* __restrict__ Vlo,
                     bf16* __restrict__ OThi, bf16* __restrict__ OTlo)
{
    extern __shared__ char smem[];
    const uint32_t sb = smem_u32(smem);
    const uint32_t QH = sb + 2 * ATT_STAGE, QL = QH + 16384;
    const int tid = threadIdx.x;
    const int wid = tid >> 5, lane = tid & 31;
    const int mt = blockIdx.x;
    const int bh = blockIdx.y;
    const int b = bh >> 4, h = bh & 15;
    const int l0 = mt * 128;

    {
        const bf16* qh = Qhi + (size_t)(b * NL + l0) * D_MODEL + h * DH;
        const bf16* ql = Qlo + (size_t)(b * NL + l0) * D_MODEL + h * DH;
        #pragma unroll
        for (int i = 0; i < 4; i++) {
            int u = tid + i * 256;
            int row = u >> 3, c8 = u & 7;
            uint32_t sw = row * 128 + ((c8 ^ (row & 7)) << 4);
            CP_ASYNC16(QH + sw, qh + (size_t)row * D_MODEL + c8 * 8);
            CP_ASYNC16(QL + sw, ql + (size_t)row * D_MODEL + c8 * 8);
        }
        CP_COMMIT();
    }

    const bf16* kph = KPhi + (size_t)bh * NL * DH;
    const bf16* kpl = KPlo + (size_t)bh * NL * DH;
    const bf16* vh  = Vhi + (size_t)b * NL * D_MODEL + h * DH;
    const bf16* vl  = Vlo + (size_t)b * NL * D_MODEL + h * DH;

    auto issue_stage = [&](int nc, int s) {
        const uint32_t stb = sb + s * ATT_STAGE;
        #pragma unroll
        for (int i = 0; i < 2; i++) {
            int u = tid + i * 256;
            int row = u >> 3, c8 = u & 7;
            uint32_t sw = row * 128 + ((c8 ^ (row & 7)) << 4);
            CP_ASYNC16(stb + sw,         kph + (size_t)(nc * 64 + row) * DH + c8 * 8);
            CP_ASYNC16(stb + 8192 + sw,  kpl + (size_t)(nc * 64 + row) * DH + c8 * 8);
            CP_ASYNC16(stb + 16384 + sw, vh + (size_t)(nc * 64 + row) * D_MODEL + c8 * 8);
            CP_ASYNC16(stb + 24576 + sw, vl + (size_t)(nc * 64 + row) * D_MODEL + c8 * 8);
        }
        CP_COMMIT();
    };

    issue_stage(0, 0);
    CP_WAIT(0);
    __syncthreads();

    uint32_t qh[4][4], ql[4][4];
    const int r0 = wid * 16;
    const int frow = r0 + (lane & 15);
    const int fsub = lane >> 4;
    #pragma unroll
    for (int kk = 0; kk < 4; kk++) {
        uint32_t off = frow * 128 + (((kk * 2 + fsub) ^ (frow & 7)) << 4);
        ldmx4(qh[kk], QH + off);
        ldmx4(ql[kk], QL + off);
    }

    const int g      = lane >> 3;
    const int b_noff = ((g & 2) << 2) + (lane & 7);
    const int b_sub  = g & 1;

    float mM[2] = { -1e30f, -1e30f }, lS[2] = { 0.f, 0.f };
    float o[8][4] = {};

    for (int nc = 0; nc < 16; nc++) {
        if (nc > 0) { CP_WAIT(0); __syncthreads(); }
        if (nc + 1 < 16) issue_stage(nc + 1, (nc + 1) & 1);
        const uint32_t stb = sb + (nc & 1) * ATT_STAGE;

        float sc[8][4] = {};
        #pragma unroll
        for (int kk = 0; kk < 4; kk++) {
            uint32_t kb[4][4], klo[4][4];
            #pragma unroll
            for (int ng = 0; ng < 4; ng++) {
                int nr = ng * 16 + b_noff;
                uint32_t off = nr * 128 + (((kk * 2 + b_sub) ^ (nr & 7)) << 4);
                ldmx4(kb[ng], stb + off);
                ldmx4(klo[ng], stb + 8192 + off);
            }
            #pragma unroll
            for (int ng = 0; ng < 4; ng++)
                #pragma unroll
                for (int hf = 0; hf < 2; hf++) {
                    float* a = sc[ng * 2 + hf];
                    mma_bf16(a, qh[kk], &kb[ng][hf * 2]);
                    mma_bf16(a, ql[kk], &kb[ng][hf * 2]);
                    mma_bf16(a, qh[kk], &klo[ng][hf * 2]);
                }
        }

        float rmax0 = -1e30f, rmax1 = -1e30f;
        #pragma unroll
        for (int t = 0; t < 8; t++) {
            rmax0 = fmaxf(rmax0, fmaxf(sc[t][0], sc[t][1]));
            rmax1 = fmaxf(rmax1, fmaxf(sc[t][2], sc[t][3]));
        }
        #pragma unroll
        for (int off = 1; off <= 2; off <<= 1) {
            rmax0 = fmaxf(rmax0, __shfl_xor_sync(0xffffffffu, rmax0, off));
            rmax1 = fmaxf(rmax1, __shfl_xor_sync(0xffffffffu, rmax1, off));
        }
        float nM0 = fmaxf(mM[0], rmax0), nM1 = fmaxf(mM[1], rmax1);
        float cor0 = __expf(mM[0] - nM0), cor1 = __expf(mM[1] - nM1);
        mM[0] = nM0; mM[1] = nM1;

        float ps0 = 0.f, ps1 = 0.f;
        #pragma unroll
        for (int t = 0; t < 8; t++) {
            sc[t][0] = __expf(sc[t][0] - nM0);
            sc[t][1] = __expf(sc[t][1] - nM0);
            sc[t][2] = __expf(sc[t][2] - nM1);
            sc[t][3] = __expf(sc[t][3] - nM1);
            ps0 += sc[t][0] + sc[t][1];
            ps1 += sc[t][2] + sc[t][3];
        }
        #pragma unroll
        for (int off = 1; off <= 2; off <<= 1) {
            ps0 += __shfl_xor_sync(0xffffffffu, ps0, off);
            ps1 += __shfl_xor_sync(0xffffffffu, ps1, off);
        }
        lS[0] = lS[0] * cor0 + ps0;
        lS[1] = lS[1] * cor1 + ps1;
        #pragma unroll
        for (int t = 0; t < 8; t++) {
            o[t][0] *= cor0; o[t][1] *= cor0;
            o[t][2] *= cor1; o[t][3] *= cor1;
        }

        #pragma unroll
        for (int kk = 0; kk < 4; kk++) {
            uint32_t vb[4][4], vlo[4][4];
            #pragma unroll
            for (int ng = 0; ng < 4; ng++) {
                int srow = kk * 16 + (lane & 7) + 8 * ((lane >> 3) & 1);
                uint32_t c8 = 2 * ng + (lane >> 4);
                uint32_t off = srow * 128 + ((c8 ^ (srow & 7)) << 4);
                ldmx4t(vb[ng], stb + 16384 + off);
                ldmx4t(vlo[ng], stb + 24576 + off);
            }
            uint32_t pa[4], pal[4];
            split_pack(sc[2 * kk][0],     sc[2 * kk][1],     pa[0], pal[0]);
            split_pack(sc[2 * kk][2],     sc[2 * kk][3],     pa[1], pal[1]);
            split_pack(sc[2 * kk + 1][0], sc[2 * kk + 1][1], pa[2], pal[2]);
            split_pack(sc[2 * kk + 1][2], sc[2 * kk + 1][3], pa[3], pal[3]);
            #pragma unroll
            for (int ng = 0; ng < 4; ng++)
                #pragma unroll
                for (int hf = 0; hf < 2; hf++) {
                    float* c = o[ng * 2 + hf];
                    mma_bf16(c, pa, &vb[ng][hf * 2]);
                    mma_bf16(c, pal, &vb[ng][hf * 2]);
                    mma_bf16(c, pa, &vlo[ng][hf * 2]);
                }
        }
    }
    __syncthreads();

    float inv0 = 1.0f / lS[0], inv1 = 1.0f / lS[1];
    float* sOT = (float*)smem;
    const int orow = lane >> 2, ocol = (lane & 3) * 2;
    #pragma unroll
    for (int t = 0; t < 8; t++) {
        int d = t * 8 + ocol;
        sOT[(d + 0) * 132 + r0 + orow]     = o[t][0] * inv0;
        sOT[(d + 1) * 132 + r0 + orow]     = o[t][1] * inv0;
        sOT[(d + 0) * 132 + r0 + orow + 8] = o[t][2] * inv1;
        sOT[(d + 1) * 132 + r0 + orow + 8] = o[t][3] * inv1;
    }
    __syncthreads();

    {
        const int d = tid >> 2;
        const int mseg = (tid & 3) * 32;
        size_t gro = (size_t)(b * NL + h * DH + d) * NL + l0 + mseg;
        #pragma unroll
        for (int j = 0; j < 32; j += 2) {
            float f0 = sOT[d * 132 + mseg + j];
            float f1 = sOT[d * 132 + mseg + j + 1];
            uint32_t hp, lp;
            split_pack(f0, f1, hp, lp);
            *(uint32_t*)(OThi + gro + j) = hp;
            *(uint32_t*)(OTlo + gro + j) = lp;
        }
    }
}

// ============================================================================
// Launch — multi-stream fork/join (graph-capture-safe)
// ============================================================================
extern "C" void kernel_launch(void* const* d_in, const int* in_sizes, int n_in,
                              void* d_out, int out_size)
{
    const float* queries = (const float*)d_in[0];
    const float* keys    = (const float*)d_in[1];
    const float* values  = (const float*)d_in[2];
    const float* routers = (const float*)d_in[3];
    const float* Wq      = (const float*)d_in[4];
    const float* Wk      = (const float*)d_in[5];
    const float* Wv      = (const float*)d_in[6];
    const float* Wlq     = (const float*)d_in[7];
    const float* Wlk     = (const float*)d_in[8];
    const float* Wo      = (const float*)d_in[9];
    const float* bo      = (const float*)d_in[10];
    float* out           = (float*)d_out;

    float *Kp, *RQ, *RK, *WEP;
    bf16 *QAhi, *QAlo, *KAhi, *KAlo, *VAhi, *VAlo, *RAhi, *RAlo;
    bf16 *WQhi, *WQlo, *WKhi, *WKlo, *WVhi, *WVlo, *WLQhi, *WLQlo, *WLKhi, *WLKlo, *WOhi, *WOlo;
    bf16 *Qhi, *Qlo, *Vhi, *Vlo, *KPhi, *KPlo, *OThi, *OTlo;
    cudaGetSymbolAddress((void**)&Kp,    g_K);
    cudaGetSymbolAddress((void**)&RQ,    g_RQ);
    cudaGetSymbolAddress((void**)&RK,    g_RK);
    cudaGetSymbolAddress((void**)&WEP,   g_WEP);
    cudaGetSymbolAddress((void**)&QAhi,  g_QAhi);
    cudaGetSymbolAddress((void**)&QAlo,  g_QAlo);
    cudaGetSymbolAddress((void**)&KAhi,  g_KAhi);
    cudaGetSymbolAddress((void**)&KAlo,  g_KAlo);
    cudaGetSymbolAddress((void**)&VAhi,  g_VAhi);
    cudaGetSymbolAddress((void**)&VAlo,  g_VAlo);
    cudaGetSymbolAddress((void**)&RAhi,  g_RAhi);
    cudaGetSymbolAddress((void**)&RAlo,  g_RAlo);
    cudaGetSymbolAddress((void**)&WQhi,  g_WQhi);
    cudaGetSymbolAddress((void**)&WQlo,  g_WQlo);
    cudaGetSymbolAddress((void**)&WKhi,  g_WKhi);
    cudaGetSymbolAddress((void**)&WKlo,  g_WKlo);
    cudaGetSymbolAddress((void**)&WVhi,  g_WVhi);
    cudaGetSymbolAddress((void**)&WVlo,  g_WVlo);
    cudaGetSymbolAddress((void**)&WLQhi, g_WLQhi);
    cudaGetSymbolAddress((void**)&WLQlo, g_WLQlo);
    cudaGetSymbolAddress((void**)&WLKhi, g_WLKhi);
    cudaGetSymbolAddress((void**)&WLKlo, g_WLKlo);
    cudaGetSymbolAddress((void**)&WOhi,  g_WOhi);
    cudaGetSymbolAddress((void**)&WOlo,  g_WOlo);
    cudaGetSymbolAddress((void**)&Qhi,   g_Qhi);
    cudaGetSymbolAddress((void**)&Qlo,   g_Qlo);
    cudaGetSymbolAddress((void**)&Vhi,   g_Vhi);
    cudaGetSymbolAddress((void**)&Vlo,   g_Vlo);
    cudaGetSymbolAddress((void**)&KPhi,  g_KPhi);
    cudaGetSymbolAddress((void**)&KPlo,  g_KPlo);
    cudaGetSymbolAddress((void**)&OThi,  g_OThi);
    cudaGetSymbolAddress((void**)&OTlo,  g_OTlo);

    const int M  = NB * NL;
    const int Mr = NB * NG;
    const int N  = D_MODEL, K = D_MODEL;

    cudaFuncSetAttribute(gemm_mma_kernel,
                         cudaFuncAttributeMaxDynamicSharedMemorySize, GEMM_SMEM);
    cudaFuncSetAttribute(attn_mma_kernel,
                         cudaFuncAttributeMaxDynamicSharedMemorySize, ATT_SMEM);

    static cudaStream_t s1 = nullptr, s2 = nullptr, s3 = nullptr;
    static cudaEvent_t ev0 = nullptr, evQ = nullptr, evV = nullptr,
                       evR = nullptr, evWo = nullptr;
    if (!s1) {
        cudaStreamCreateWithFlags(&s1, cudaStreamNonBlocking);
        cudaStreamCreateWithFlags(&s2, cudaStreamNonBlocking);
        cudaStreamCreateWithFlags(&s3, cudaStreamNonBlocking);
        cudaEventCreateWithFlags(&ev0, cudaEventDisableTiming);
        cudaEventCreateWithFlags(&evQ, cudaEventDisableTiming);
        cudaEventCreateWithFlags(&evV, cudaEventDisableTiming);
        cudaEventCreateWithFlags(&evR, cudaEventDisableTiming);
        cudaEventCreateWithFlags(&evWo, cudaEventDisableTiming);
    }

    dim3 cw(32, 32);
    dim3 gBig(N / 128, M / 128);
    dim3 gRtr(N / 128, Mr / 128);
    const int nBig = M * K, nRtr = Mr * K;

    cudaEventRecord(ev0, 0);
    cudaStreamWaitEvent(s1, ev0, 0);
    cudaStreamWaitEvent(s2, ev0, 0);
    cudaStreamWaitEvent(s3, ev0, 0);

    // ---- main stream: critical path (K chain) ----
    conv_hilo_kernel<<<nBig / 1024, 256>>>(keys, KAhi, KAlo, nBig);
    conv_wt_kernel<<<cw, 256>>>(Wk, WKhi, WKlo);
    gemm_mma_kernel<<<gBig, 256, GEMM_SMEM>>>(KAhi, KAlo, WKhi, WKlo, Kp, nullptr, nullptr, nullptr, M, N, K);

    // ---- s1: Q chain ----
    conv_hilo_kernel<<<nBig / 1024, 256, 0, s1>>>(queries, QAhi, QAlo, nBig);
    conv_wt_kernel<<<cw, 256, 0, s1>>>(Wq, WQhi, WQlo);
    gemm_mma_kernel<<<gBig, 256, GEMM_SMEM, s1>>>(QAhi, QAlo, WQhi, WQlo, nullptr, nullptr, Qhi, Qlo, M, N, K);
    cudaEventRecord(evQ, s1);

    // ---- s2: V chain ----
    conv_hilo_kernel<<<nBig / 1024, 256, 0, s2>>>(values, VAhi, VAlo, nBig);
    conv_wt_kernel<<<cw, 256, 0, s2>>>(Wv, WVhi, WVlo);
    gemm_mma_kernel<<<gBig, 256, GEMM_SMEM, s2>>>(VAhi, VAlo, WVhi, WVlo, nullptr, nullptr, Vhi, Vlo, M, N, K);
    cudaEventRecord(evV, s2);

    // ---- s3: router chain + Wo conversion ----
    conv_hilo_kernel<<<nRtr / 1024, 256, 0, s3>>>(routers, RAhi, RAlo, nRtr);
    conv_wt_kernel<<<cw, 256, 0, s3>>>(Wlq, WLQhi, WLQlo);
    gemm_mma_kernel<<<gRtr, 256, GEMM_SMEM, s3>>>(RAhi, RAlo, WLQhi, WLQlo, RQ, nullptr, nullptr, nullptr, Mr, N, K);
    conv_wt_kernel<<<cw, 256, 0, s3>>>(Wlk, WLKhi, WLKlo);
    gemm_mma_kernel<<<gRtr, 256, GEMM_SMEM, s3>>>(RAhi, RAlo, WLKhi, WLKlo, RK, nullptr, nullptr, nullptr, Mr, N, K);
    wep_kernel<<<NB * NH, 256, 0, s3>>>(RQ, RK, WEP);
    cudaEventRecord(evR, s3);
    conv_wt_kernel<<<cw, 256, 0, s3>>>(Wo, WOhi, WOlo);
    cudaEventRecord(evWo, s3);

    // ---- main: kprime (needs K + WEP) ----
    cudaStreamWaitEvent(0, evR, 0);
    dim3 gKP(NL / 64, NB * NH);
    kprime_kernel<<<gKP, 256>>>(Kp, WEP, KPhi, KPlo);

    // ---- main: attention (needs Q, V, KP) ----
    cudaStreamWaitEvent(0, evQ, 0);
    cudaStreamWaitEvent(0, evV, 0);
    dim3 gAtt(NL / 128, NB * NH);
    attn_mma_kernel<<<gAtt, 256, ATT_SMEM>>>(Qhi, Qlo, KPhi, KPlo, Vhi, Vlo, OThi, OTlo);

    // ---- main: final GEMM with bias ----
    cudaStreamWaitEvent(0, evWo, 0);
    gemm_mma_kernel<<<gBig, 256, GEMM_SMEM>>>(OThi, OTlo, WOhi, WOlo, out, bo, nullptr, nullptr, M, N, K);
}